// round 1
// baseline (speedup 1.0000x reference)
#include <cuda_runtime.h>
#include <math.h>

// ---------------------------------------------------------------------------
// Problem constants
// ---------------------------------------------------------------------------
#define BATCH 8
#define HDIM 64
#define WDIM 64
#define CC 512
#define C8 64      // f/g channels
#define C2 256     // h channels
#define NPIX 4096          // H*W
#define NPOOL 1024         // (H/2)*(W/2)
#define NCAT 384           // 64 + 64 + 256
// column offsets inside concatenated projection
#define OFF_F 0
#define OFF_G 64
#define OFF_H 128

// ---------------------------------------------------------------------------
// Scratch (device globals; allocation-free)
// ---------------------------------------------------------------------------
__device__ float d_Wcat[CC * NCAT];                         // 0.75 MB
__device__ float d_P[(long long)BATCH * NPIX * NCAT];       // 48 MB   full-res [f|g|h]
__device__ float d_F[BATCH * NPOOL * C8];                   // 2 MB    pooled f
__device__ float d_Hh[BATCH * NPOOL * C2];                  // 8 MB    pooled h
__device__ float d_S[(long long)BATCH * NPIX * NPOOL];      // 128 MB  scores / beta
__device__ float d_O[(long long)BATCH * NPIX * C2];         // 32 MB   beta @ h

// ---------------------------------------------------------------------------
// Generic tiled SGEMM: C[M,N] = A[M,K] * B  (B either [K,N] or, if BT, [N,K])
// 128x128 block, 16 k-slice, 8x8 per-thread microtile, 256 threads.
// Optional epilogue: C = gamma[0]*acc + resid  (resid has C's layout).
// All M,N,K here are multiples of the tile sizes; loads are float4-aligned.
// ---------------------------------------------------------------------------
#define BM 128
#define BN 128
#define BK 16
#define TM 8
#define TN 8

template <bool BT, bool EPI>
__global__ void __launch_bounds__(256) sgemm_kernel(
    const float* __restrict__ A, int lda, long long strideA,
    const float* __restrict__ B, int ldb, long long strideB,
    float* __restrict__ C, int ldc, long long strideC,
    int M, int N, int K,
    const float* __restrict__ resid, const float* __restrict__ gamma)
{
    A += strideA * blockIdx.z;
    B += strideB * blockIdx.z;
    C += strideC * blockIdx.z;

    const int m0 = blockIdx.y * BM;
    const int n0 = blockIdx.x * BN;
    const int tid = threadIdx.x;
    const int tx = tid & 15;   // 16 thread columns
    const int ty = tid >> 4;   // 16 thread rows

    __shared__ float As[BK][BM];
    __shared__ float Bs[BK][BN];

    float acc[TM][TN];
#pragma unroll
    for (int i = 0; i < TM; i++)
#pragma unroll
        for (int j = 0; j < TN; j++) acc[i][j] = 0.f;

    const int aRow = tid >> 2;        // 0..63
    const int aC4  = (tid & 3) * 4;   // 0,4,8,12
    const int bRow = tid >> 5;        // 0..7
    const int bC4  = (tid & 31) * 4;  // 0..124

    for (int k0 = 0; k0 < K; k0 += BK) {
        // --- A tile: [BM, BK] transposed into As[k][m] ---
#pragma unroll
        for (int it = 0; it < 2; it++) {
            int r = aRow + it * 64;
            float4 v = *reinterpret_cast<const float4*>(
                &A[(long long)(m0 + r) * lda + k0 + aC4]);
            As[aC4 + 0][r] = v.x;
            As[aC4 + 1][r] = v.y;
            As[aC4 + 2][r] = v.z;
            As[aC4 + 3][r] = v.w;
        }
        // --- B tile ---
        if (!BT) {
#pragma unroll
            for (int it = 0; it < 2; it++) {
                int r = bRow + it * 8;
                float4 v = *reinterpret_cast<const float4*>(
                    &B[(long long)(k0 + r) * ldb + n0 + bC4]);
                *reinterpret_cast<float4*>(&Bs[r][bC4]) = v;
            }
        } else {
            // B stored [N, K]; Bs[k][n] = B[n, k]
#pragma unroll
            for (int it = 0; it < 2; it++) {
                int n = aRow + it * 64;
                float4 v = *reinterpret_cast<const float4*>(
                    &B[(long long)(n0 + n) * ldb + k0 + aC4]);
                Bs[aC4 + 0][n] = v.x;
                Bs[aC4 + 1][n] = v.y;
                Bs[aC4 + 2][n] = v.z;
                Bs[aC4 + 3][n] = v.w;
            }
        }
        __syncthreads();

#pragma unroll
        for (int kk = 0; kk < BK; kk++) {
            float a[TM], b[TN];
#pragma unroll
            for (int i = 0; i < TM; i++) a[i] = As[kk][ty * TM + i];
#pragma unroll
            for (int j = 0; j < TN; j++) b[j] = Bs[kk][tx * TN + j];
#pragma unroll
            for (int i = 0; i < TM; i++)
#pragma unroll
                for (int j = 0; j < TN; j++) acc[i][j] += a[i] * b[j];
        }
        __syncthreads();
    }

    const float gm = EPI ? gamma[0] : 0.f;
#pragma unroll
    for (int i = 0; i < TM; i++) {
        long long row = m0 + ty * TM + i;
#pragma unroll
        for (int j = 0; j < TN; j += 4) {
            long long off = row * ldc + n0 + tx * TN + j;
            float4 v;
            v.x = acc[i][j + 0];
            v.y = acc[i][j + 1];
            v.z = acc[i][j + 2];
            v.w = acc[i][j + 3];
            if (EPI) {
                float4 rv = *reinterpret_cast<const float4*>(&resid[off]);
                v.x = gm * v.x + rv.x;
                v.y = gm * v.y + rv.y;
                v.z = gm * v.z + rv.z;
                v.w = gm * v.w + rv.w;
            }
            *reinterpret_cast<float4*>(&C[off]) = v;
        }
    }
}

// ---------------------------------------------------------------------------
// Concatenate wf|wg|wh into d_Wcat [512, 384]
// ---------------------------------------------------------------------------
__global__ void concat_w_kernel(const float* __restrict__ wf,
                                const float* __restrict__ wg,
                                const float* __restrict__ wh)
{
    int idx = blockIdx.x * blockDim.x + threadIdx.x;
    if (idx >= CC * NCAT) return;
    int k = idx / NCAT;
    int j = idx % NCAT;
    float v;
    if (j < 64)       v = wf[k * C8 + j];
    else if (j < 128) v = wg[k * C8 + (j - 64)];
    else              v = wh[k * C2 + (j - 128)];
    d_Wcat[idx] = v;
}

// ---------------------------------------------------------------------------
// 2x2 max pool of the f (cols 0:64) and h (cols 128:384) slices of d_P
// into d_F [B,1024,64] and d_Hh [B,1024,256]
// ---------------------------------------------------------------------------
__global__ void pool_kernel()
{
    int idx = blockIdx.x * blockDim.x + threadIdx.x;
    const int total = BATCH * NPOOL * (C8 + C2);  // 320 channels per pooled pixel
    if (idx >= total) return;
    int c = idx % (C8 + C2);
    int p = (idx / (C8 + C2)) % NPOOL;
    int b = idx / ((C8 + C2) * NPOOL);
    int ph = p >> 5;          // pooled grid is 32x32
    int pw = p & 31;
    int col = (c < C8) ? (OFF_F + c) : (OFF_H + (c - C8));
    const float* base = d_P + (long long)b * NPIX * NCAT;
    int r0 = (2 * ph) * WDIM + 2 * pw;
    float v0 = base[(long long)(r0) * NCAT + col];
    float v1 = base[(long long)(r0 + 1) * NCAT + col];
    float v2 = base[(long long)(r0 + WDIM) * NCAT + col];
    float v3 = base[(long long)(r0 + WDIM + 1) * NCAT + col];
    float v = fmaxf(fmaxf(v0, v1), fmaxf(v2, v3));
    if (c < C8) d_F[((long long)b * NPOOL + p) * C8 + c] = v;
    else        d_Hh[((long long)b * NPOOL + p) * C2 + (c - C8)] = v;
}

// ---------------------------------------------------------------------------
// Row softmax over d_S, in place. One block (256 threads) per row of 1024.
// ---------------------------------------------------------------------------
__global__ void __launch_bounds__(256) softmax_kernel(float* __restrict__ S, int cols)
{
    float* row = S + (long long)blockIdx.x * cols;
    const int tid = threadIdx.x;
    __shared__ float red[32];

    // max
    float m = -1e30f;
    for (int c = tid; c < cols; c += 256) m = fmaxf(m, row[c]);
#pragma unroll
    for (int o = 16; o > 0; o >>= 1) m = fmaxf(m, __shfl_xor_sync(0xffffffffu, m, o));
    if ((tid & 31) == 0) red[tid >> 5] = m;
    __syncthreads();
    if (tid < 32) {
        float v = (tid < 8) ? red[tid] : -1e30f;
#pragma unroll
        for (int o = 16; o > 0; o >>= 1) v = fmaxf(v, __shfl_xor_sync(0xffffffffu, v, o));
        red[tid] = v;
    }
    __syncthreads();
    m = red[0];
    __syncthreads();

    // exp + sum
    float sum = 0.f;
    for (int c = tid; c < cols; c += 256) {
        float e = __expf(row[c] - m);
        row[c] = e;
        sum += e;
    }
#pragma unroll
    for (int o = 16; o > 0; o >>= 1) sum += __shfl_xor_sync(0xffffffffu, sum, o);
    if ((tid & 31) == 0) red[tid >> 5] = sum;
    __syncthreads();
    if (tid < 32) {
        float v = (tid < 8) ? red[tid] : 0.f;
#pragma unroll
        for (int o = 16; o > 0; o >>= 1) v += __shfl_xor_sync(0xffffffffu, v, o);
        red[tid] = v;
    }
    __syncthreads();
    float inv = 1.f / red[0];
    for (int c = tid; c < cols; c += 256) row[c] *= inv;
}

// ---------------------------------------------------------------------------
// Launch
// ---------------------------------------------------------------------------
extern "C" void kernel_launch(void* const* d_in, const int* in_sizes, int n_in,
                              void* d_out, int out_size)
{
    const float* x     = (const float*)d_in[0];
    const float* wf    = (const float*)d_in[1];
    const float* wg    = (const float*)d_in[2];
    const float* wh    = (const float*)d_in[3];
    const float* wo    = (const float*)d_in[4];
    const float* gamma = (const float*)d_in[5];
    float* out = (float*)d_out;

    float *pWcat, *pP, *pF, *pH, *pS, *pO;
    cudaGetSymbolAddress((void**)&pWcat, d_Wcat);
    cudaGetSymbolAddress((void**)&pP, d_P);
    cudaGetSymbolAddress((void**)&pF, d_F);
    cudaGetSymbolAddress((void**)&pH, d_Hh);
    cudaGetSymbolAddress((void**)&pS, d_S);
    cudaGetSymbolAddress((void**)&pO, d_O);

    // 1) concat weights -> Wcat [512, 384]
    concat_w_kernel<<<(CC * NCAT + 255) / 256, 256>>>(wf, wg, wh);

    // 2) P = x @ Wcat     (M=32768, K=512, N=384)
    {
        dim3 grid(NCAT / BN, (BATCH * NPIX) / BM, 1);
        sgemm_kernel<false, false><<<grid, 256>>>(
            x, CC, 0, pWcat, NCAT, 0, pP, NCAT, 0,
            BATCH * NPIX, NCAT, CC, nullptr, nullptr);
    }

    // 3) 2x2 max pool -> F [B,1024,64], H [B,1024,256]
    pool_kernel<<<(BATCH * NPOOL * (C8 + C2) + 255) / 256, 256>>>();

    // 4) S[b] = G[b] @ F[b]^T   (M=4096, N=1024, K=64), G = P cols 64:128
    {
        dim3 grid(NPOOL / BN, NPIX / BM, BATCH);
        sgemm_kernel<true, false><<<grid, 256>>>(
            pP + OFF_G, NCAT, (long long)NPIX * NCAT,
            pF, C8, (long long)NPOOL * C8,
            pS, NPOOL, (long long)NPIX * NPOOL,
            NPIX, NPOOL, C8, nullptr, nullptr);
    }

    // 5) softmax rows of S (in place -> beta)
    softmax_kernel<<<BATCH * NPIX, 256>>>(pS, NPOOL);

    // 6) O[b] = beta[b] @ H[b]  (M=4096, N=256, K=1024)
    {
        dim3 grid(C2 / BN, NPIX / BM, BATCH);
        sgemm_kernel<false, false><<<grid, 256>>>(
            pS, NPOOL, (long long)NPIX * NPOOL,
            pH, C2, (long long)NPOOL * C2,
            pO, C2, (long long)NPIX * C2,
            NPIX, C2, NPOOL, nullptr, nullptr);
    }

    // 7) out = gamma * (O @ wo) + x   (M=32768, K=256, N=512)
    {
        dim3 grid(CC / BN, (BATCH * NPIX) / BM, 1);
        sgemm_kernel<false, true><<<grid, 256>>>(
            pO, C2, 0, wo, CC, 0, out, CC, 0,
            BATCH * NPIX, CC, C2, x, gamma);
    }
}

// round 3
// speedup vs baseline: 2.4484x; 2.4484x over previous
#include <cuda_runtime.h>
#include <cstdint>
#include <math.h>

// ---------------------------------------------------------------------------
// Problem constants
// ---------------------------------------------------------------------------
#define BATCH 8
#define WDIM 64
#define CC 512
#define C8 64
#define C2 256
#define NPIX 4096
#define NPOOL 1024
#define NCAT 384
#define OFF_F 0
#define OFF_G 64
#define OFF_H 128

// ---------------------------------------------------------------------------
// Scratch (device globals; allocation-free)
// ---------------------------------------------------------------------------
__device__ float d_Wcat[CC * NCAT];                     // 0.75 MB
__device__ float d_P[(long long)BATCH * NPIX * NCAT];   // 48 MB
__device__ float d_Ft[BATCH * C8 * NPOOL];              // 2 MB  (pooled f, TRANSPOSED [C8, NPOOL])
__device__ float d_Hh[BATCH * NPOOL * C2];              // 8 MB
__device__ float d_S[(long long)BATCH * NPIX * NPOOL];  // 128 MB
__device__ float d_O[(long long)BATCH * NPIX * C2];     // 32 MB

// ---------------------------------------------------------------------------
// Helpers
// ---------------------------------------------------------------------------
__device__ __forceinline__ uint32_t smem_u32(const void* p) {
    uint32_t a;
    asm("{ .reg .u64 t; cvta.to.shared.u64 t, %1; cvt.u32.u64 %0, t; }" : "=r"(a) : "l"(p));
    return a;
}
__device__ __forceinline__ void cp16(uint32_t dst, const float* src) {
    asm volatile("cp.async.cg.shared.global [%0], [%1], 16;" ::"r"(dst), "l"(src));
}
#define CP_COMMIT() asm volatile("cp.async.commit_group;" ::: "memory")

__device__ __forceinline__ void mma_tf32(float* d, const uint32_t* a, const uint32_t* b) {
    asm volatile(
        "mma.sync.aligned.m16n8k8.row.col.f32.tf32.tf32.f32 "
        "{%0,%1,%2,%3}, {%4,%5,%6,%7}, {%8,%9}, {%0,%1,%2,%3};"
        : "+f"(d[0]), "+f"(d[1]), "+f"(d[2]), "+f"(d[3])
        : "r"(a[0]), "r"(a[1]), "r"(a[2]), "r"(a[3]), "r"(b[0]), "r"(b[1]));
}

// ---------------------------------------------------------------------------
// tf32 mma.sync GEMM: C[M,N] = A[M,K] * B[K,N]
// CTA tile 256x64, BK=32, 8 warps (4m x 2n), warp tile 64x32.
// cp.async double-buffered smem. EPI: C = gamma[0]*acc + resid.
// ---------------------------------------------------------------------------
#define ASTRIDE 40   // words per A row (128B-pad -> conflict-free frag LDS)
#define BSTRIDE 72   // words per B row
#define ASTG (256 * ASTRIDE * 4)
#define BSTG (32 * BSTRIDE * 4)
#define SMEM_TOTAL (2 * (ASTG + BSTG))

template <bool EPI>
__global__ void __launch_bounds__(256, 1) mma_gemm(
    const float* __restrict__ A, int lda, long long sA,
    const float* __restrict__ B, int ldb, long long sB,
    float* __restrict__ C, int ldc, long long sC,
    int K, const float* __restrict__ resid, const float* __restrict__ gamma)
{
    extern __shared__ __align__(16) char smem[];
    A += sA * blockIdx.z;
    B += sB * blockIdx.z;
    C += sC * blockIdx.z;

    const int m0 = blockIdx.y * 256;
    const int n0 = blockIdx.x * 64;
    const int tid = threadIdx.x;
    const int wid = tid >> 5, lane = tid & 31;
    const int gid = lane >> 2, tig = lane & 3;
    const int wm = (wid & 3) * 64;   // warp m-offset
    const int wn = (wid >> 2) * 32;  // warp n-offset

    const uint32_t sb = smem_u32(smem);
    const uint32_t aB[2] = {sb, sb + ASTG + BSTG};
    const uint32_t bB[2] = {sb + ASTG, sb + 2 * ASTG + BSTG};

    const int KT = K / 32;

    // ---- async tile issue ----
    auto issue = [&](int kt, int s) {
        const float* Ap = A + (long long)m0 * lda + kt * 32;
#pragma unroll
        for (int it = 0; it < 8; it++) {
            int idx = tid + it * 256;
            int r = idx >> 3, kk = idx & 7;
            cp16(aB[s] + (uint32_t)((r * ASTRIDE + kk * 4) * 4),
                 Ap + (long long)r * lda + kk * 4);
        }
        const float* Bp = B + (long long)(kt * 32) * ldb + n0;
#pragma unroll
        for (int it = 0; it < 2; it++) {
            int idx = tid + it * 256;
            int r = idx >> 4, c = idx & 15;
            cp16(bB[s] + (uint32_t)((r * BSTRIDE + c * 4) * 4),
                 Bp + (long long)r * ldb + c * 4);
        }
        CP_COMMIT();
    };

    float acc[4][4][4];
#pragma unroll
    for (int i = 0; i < 4; i++)
#pragma unroll
        for (int j = 0; j < 4; j++)
#pragma unroll
            for (int k = 0; k < 4; k++) acc[i][j][k] = 0.f;

    issue(0, 0);
    issue(1, 1);

    for (int kt = 0; kt < KT; kt++) {
        const int s = kt & 1;
        if (kt < KT - 1) asm volatile("cp.async.wait_group 1;" ::: "memory");
        else             asm volatile("cp.async.wait_group 0;" ::: "memory");
        __syncthreads();

        const uint32_t* AsU = (const uint32_t*)(smem + (s ? ASTG + BSTG : 0));
        const uint32_t* BsU = (const uint32_t*)(smem + ASTG + (s ? ASTG + BSTG : 0));

#pragma unroll
        for (int k8 = 0; k8 < 4; k8++) {
            uint32_t a[4][4], b[4][2];
#pragma unroll
            for (int mt = 0; mt < 4; mt++) {
                int r = wm + mt * 16 + gid;
                int c = k8 * 8 + tig;
                a[mt][0] = AsU[r * ASTRIDE + c];
                a[mt][1] = AsU[(r + 8) * ASTRIDE + c];
                a[mt][2] = AsU[r * ASTRIDE + c + 4];
                a[mt][3] = AsU[(r + 8) * ASTRIDE + c + 4];
            }
#pragma unroll
            for (int nt = 0; nt < 4; nt++) {
                int kr = k8 * 8 + tig;
                int cn = wn + nt * 8 + gid;
                b[nt][0] = BsU[kr * BSTRIDE + cn];
                b[nt][1] = BsU[(kr + 4) * BSTRIDE + cn];
            }
#pragma unroll
            for (int mt = 0; mt < 4; mt++)
#pragma unroll
                for (int nt = 0; nt < 4; nt++)
                    mma_tf32(acc[mt][nt], a[mt], b[nt]);
        }
        __syncthreads();
        if (kt + 2 < KT) issue(kt + 2, s);
    }

    // ---- epilogue ----
    const float gm = EPI ? gamma[0] : 0.f;
    const float* rp = EPI ? (resid + sC * blockIdx.z) : nullptr;
#pragma unroll
    for (int mt = 0; mt < 4; mt++) {
#pragma unroll
        for (int h = 0; h < 2; h++) {
            long long row = m0 + wm + mt * 16 + gid + h * 8;
#pragma unroll
            for (int nt = 0; nt < 4; nt++) {
                long long off = row * ldc + n0 + wn + nt * 8 + 2 * tig;
                float2 v = make_float2(acc[mt][nt][h * 2], acc[mt][nt][h * 2 + 1]);
                if (EPI) {
                    float2 rv = *reinterpret_cast<const float2*>(&rp[off]);
                    v.x = fmaf(gm, v.x, rv.x);
                    v.y = fmaf(gm, v.y, rv.y);
                }
                *reinterpret_cast<float2*>(&C[off]) = v;
            }
        }
    }
}

// ---------------------------------------------------------------------------
// Concat wf|wg|wh -> Wcat [512, 384]
// ---------------------------------------------------------------------------
__global__ void concat_w_kernel(const float* __restrict__ wf,
                                const float* __restrict__ wg,
                                const float* __restrict__ wh)
{
    int idx = blockIdx.x * blockDim.x + threadIdx.x;
    if (idx >= CC * NCAT) return;
    int k = idx / NCAT;
    int j = idx % NCAT;
    float v;
    if (j < 64)       v = wf[k * C8 + j];
    else if (j < 128) v = wg[k * C8 + (j - 64)];
    else              v = wh[k * C2 + (j - 128)];
    d_Wcat[idx] = v;
}

// ---------------------------------------------------------------------------
// 2x2 max pool: f slice -> d_Ft [B, C8, NPOOL] (transposed), h -> d_Hh [B, NPOOL, C2]
// ---------------------------------------------------------------------------
__global__ void pool_kernel()
{
    int idx = blockIdx.x * blockDim.x + threadIdx.x;
    const int total = BATCH * NPOOL * (C8 + C2);
    if (idx >= total) return;
    int c = idx % (C8 + C2);
    int p = (idx / (C8 + C2)) % NPOOL;
    int b = idx / ((C8 + C2) * NPOOL);
    int ph = p >> 5;
    int pw = p & 31;
    int col = (c < C8) ? (OFF_F + c) : (OFF_H + (c - C8));
    const float* base = d_P + (long long)b * NPIX * NCAT;
    int r0 = (2 * ph) * WDIM + 2 * pw;
    float v0 = base[(long long)(r0) * NCAT + col];
    float v1 = base[(long long)(r0 + 1) * NCAT + col];
    float v2 = base[(long long)(r0 + WDIM) * NCAT + col];
    float v3 = base[(long long)(r0 + WDIM + 1) * NCAT + col];
    float v = fmaxf(fmaxf(v0, v1), fmaxf(v2, v3));
    if (c < C8) d_Ft[((long long)b * C8 + c) * NPOOL + p] = v;
    else        d_Hh[((long long)b * NPOOL + p) * C2 + (c - C8)] = v;
}

// ---------------------------------------------------------------------------
// One-pass register-resident softmax: 256 threads x float4 = 1024 cols
// ---------------------------------------------------------------------------
__global__ void __launch_bounds__(256) softmax_kernel(float* __restrict__ S)
{
    float4* row = reinterpret_cast<float4*>(S + (long long)blockIdx.x * NPOOL);
    const int tid = threadIdx.x;
    const int wid = tid >> 5, lane = tid & 31;
    __shared__ float red_m[8], red_s[8];

    float4 v = row[tid];
    float m = fmaxf(fmaxf(v.x, v.y), fmaxf(v.z, v.w));
#pragma unroll
    for (int o = 16; o > 0; o >>= 1) m = fmaxf(m, __shfl_xor_sync(0xffffffffu, m, o));
    if (lane == 0) red_m[wid] = m;
    __syncthreads();
    float mm = red_m[0];
#pragma unroll
    for (int i = 1; i < 8; i++) mm = fmaxf(mm, red_m[i]);

    v.x = __expf(v.x - mm);
    v.y = __expf(v.y - mm);
    v.z = __expf(v.z - mm);
    v.w = __expf(v.w - mm);
    float s = v.x + v.y + v.z + v.w;
#pragma unroll
    for (int o = 16; o > 0; o >>= 1) s += __shfl_xor_sync(0xffffffffu, s, o);
    if (lane == 0) red_s[wid] = s;
    __syncthreads();
    float ss = red_s[0];
#pragma unroll
    for (int i = 1; i < 8; i++) ss += red_s[i];
    float inv = 1.f / ss;
    v.x *= inv; v.y *= inv; v.z *= inv; v.w *= inv;
    row[tid] = v;
}

// ---------------------------------------------------------------------------
// Launch
// ---------------------------------------------------------------------------
extern "C" void kernel_launch(void* const* d_in, const int* in_sizes, int n_in,
                              void* d_out, int out_size)
{
    const float* x     = (const float*)d_in[0];
    const float* wf    = (const float*)d_in[1];
    const float* wg    = (const float*)d_in[2];
    const float* wh    = (const float*)d_in[3];
    const float* wo    = (const float*)d_in[4];
    const float* gamma = (const float*)d_in[5];
    float* out = (float*)d_out;

    float *pWcat, *pP, *pFt, *pH, *pS, *pO;
    cudaGetSymbolAddress((void**)&pWcat, d_Wcat);
    cudaGetSymbolAddress((void**)&pP, d_P);
    cudaGetSymbolAddress((void**)&pFt, d_Ft);
    cudaGetSymbolAddress((void**)&pH, d_Hh);
    cudaGetSymbolAddress((void**)&pS, d_S);
    cudaGetSymbolAddress((void**)&pO, d_O);

    cudaFuncSetAttribute(mma_gemm<false>,
                         cudaFuncAttributeMaxDynamicSharedMemorySize, SMEM_TOTAL);
    cudaFuncSetAttribute(mma_gemm<true>,
                         cudaFuncAttributeMaxDynamicSharedMemorySize, SMEM_TOTAL);

    // 1) concat weights
    concat_w_kernel<<<(CC * NCAT + 255) / 256, 256>>>(wf, wg, wh);

    // 2) P = x @ Wcat   (M=32768, N=384, K=512)
    mma_gemm<false><<<dim3(NCAT / 64, (BATCH * NPIX) / 256, 1), 256, SMEM_TOTAL>>>(
        x, CC, 0, pWcat, NCAT, 0, pP, NCAT, 0, CC, nullptr, nullptr);

    // 3) pool -> Ft [B,64,1024] (transposed), H [B,1024,256]
    pool_kernel<<<(BATCH * NPOOL * (C8 + C2) + 255) / 256, 256>>>();

    // 4) S[b] = G[b] @ Ft[b]   (M=4096, N=1024, K=64)
    mma_gemm<false><<<dim3(NPOOL / 64, NPIX / 256, BATCH), 256, SMEM_TOTAL>>>(
        pP + OFF_G, NCAT, (long long)NPIX * NCAT,
        pFt, NPOOL, (long long)C8 * NPOOL,
        pS, NPOOL, (long long)NPIX * NPOOL,
        C8, nullptr, nullptr);

    // 5) softmax rows
    softmax_kernel<<<BATCH * NPIX, 256>>>(pS);

    // 6) O[b] = beta[b] @ H[b]  (M=4096, N=256, K=1024)
    mma_gemm<false><<<dim3(C2 / 64, NPIX / 256, BATCH), 256, SMEM_TOTAL>>>(
        pS, NPOOL, (long long)NPIX * NPOOL,
        pH, C2, (long long)NPOOL * C2,
        pO, C2, (long long)NPIX * C2,
        NPOOL, nullptr, nullptr);

    // 7) out = gamma * (O @ wo) + x  (M=32768, N=512, K=256)
    mma_gemm<true><<<dim3(CC / 64, (BATCH * NPIX) / 256, 1), 256, SMEM_TOTAL>>>(
        pO, C2, 0, wo, CC, 0, out, CC, 0, C2, x, gamma);
}

// round 4
// speedup vs baseline: 2.4658x; 1.0071x over previous
#include <cuda_runtime.h>
#include <cstdint>
#include <math.h>

// ---------------------------------------------------------------------------
// Problem constants
// ---------------------------------------------------------------------------
#define BATCH 8
#define WDIM 64
#define CC 512
#define C8 64
#define C2 256
#define NPIX 4096
#define NPOOL 1024
#define NCAT 384
#define OFF_F 0
#define OFF_G 64
#define OFF_H 128

// ---------------------------------------------------------------------------
// Scratch (device globals; allocation-free)
// ---------------------------------------------------------------------------
__device__ float d_Wcat[CC * NCAT];                     // 0.75 MB
__device__ float d_P[(long long)BATCH * NPIX * NCAT];   // 48 MB
__device__ float d_Ft[BATCH * C8 * NPOOL];              // 2 MB  pooled f, transposed [C8, NPOOL]
__device__ float d_Hh[BATCH * NPOOL * C2];              // 8 MB
__device__ float d_O[(long long)BATCH * NPIX * C2];     // 32 MB

// ---------------------------------------------------------------------------
// Helpers
// ---------------------------------------------------------------------------
__device__ __forceinline__ uint32_t smem_u32(const void* p) {
    uint32_t a;
    asm("{ .reg .u64 t; cvta.to.shared.u64 t, %1; cvt.u32.u64 %0, t; }" : "=r"(a) : "l"(p));
    return a;
}
__device__ __forceinline__ void cp16(uint32_t dst, const float* src) {
    asm volatile("cp.async.cg.shared.global [%0], [%1], 16;" ::"r"(dst), "l"(src));
}
#define CP_COMMIT() asm volatile("cp.async.commit_group;" ::: "memory")
#define CP_WAIT0()  asm volatile("cp.async.wait_group 0;" ::: "memory")
#define CP_WAIT1()  asm volatile("cp.async.wait_group 1;" ::: "memory")

__device__ __forceinline__ void mma_tf32(float* d, const uint32_t* a, const uint32_t* b) {
    asm volatile(
        "mma.sync.aligned.m16n8k8.row.col.f32.tf32.tf32.f32 "
        "{%0,%1,%2,%3}, {%4,%5,%6,%7}, {%8,%9}, {%0,%1,%2,%3};"
        : "+f"(d[0]), "+f"(d[1]), "+f"(d[2]), "+f"(d[3])
        : "r"(a[0]), "r"(a[1]), "r"(a[2]), "r"(a[3]), "r"(b[0]), "r"(b[1]));
}

// ---------------------------------------------------------------------------
// tf32 mma.sync GEMM: C[M,N] = A[M,K] * B[K,N]
// CTA tile 256x64, BK=32, 8 warps (4m x 2n), warp tile 64x32.
// 3-stage cp.async pipeline, issue-before-compute. EPI: C = gamma*acc + resid
// ASTRIDE=36 (=4 mod 32): A-frag LDS conflict-free. BSTRIDE=72 (=8 mod 32).
// ---------------------------------------------------------------------------
#define ASTRIDE 36
#define BSTRIDE 72
#define ASTG (256 * ASTRIDE * 4)
#define BSTG (32 * BSTRIDE * 4)
#define GSTG (ASTG + BSTG)
#define SMEM_TOTAL (3 * GSTG)

template <bool EPI>
__global__ void __launch_bounds__(256, 1) mma_gemm(
    const float* __restrict__ A, int lda, long long sA,
    const float* __restrict__ B, int ldb, long long sB,
    float* __restrict__ C, int ldc, long long sC,
    int K, const float* __restrict__ resid, const float* __restrict__ gamma)
{
    extern __shared__ __align__(16) char smem[];
    A += sA * blockIdx.z;
    B += sB * blockIdx.z;
    C += sC * blockIdx.z;

    const int m0 = blockIdx.y * 256;
    const int n0 = blockIdx.x * 64;
    const int tid = threadIdx.x;
    const int wid = tid >> 5, lane = tid & 31;
    const int gid = lane >> 2, tig = lane & 3;
    const int wm = (wid & 3) * 64;
    const int wn = (wid >> 2) * 32;

    const uint32_t sb = smem_u32(smem);
    const int KT = K / 32;

    auto issue = [&](int kt, int s) {
        const uint32_t aB = sb + (uint32_t)(s * GSTG);
        const uint32_t bB = aB + ASTG;
        const float* Ap = A + (long long)m0 * lda + kt * 32;
#pragma unroll
        for (int it = 0; it < 8; it++) {
            int idx = tid + it * 256;
            int r = idx >> 3, kk = idx & 7;
            cp16(aB + (uint32_t)((r * ASTRIDE + kk * 4) * 4),
                 Ap + (long long)r * lda + kk * 4);
        }
        const float* Bp = B + (long long)(kt * 32) * ldb + n0;
#pragma unroll
        for (int it = 0; it < 2; it++) {
            int idx = tid + it * 256;
            int r = idx >> 4, c = idx & 15;
            cp16(bB + (uint32_t)((r * BSTRIDE + c * 4) * 4),
                 Bp + (long long)r * ldb + c * 4);
        }
        CP_COMMIT();
    };

    float acc[4][4][4];
#pragma unroll
    for (int i = 0; i < 4; i++)
#pragma unroll
        for (int j = 0; j < 4; j++)
#pragma unroll
            for (int k = 0; k < 4; k++) acc[i][j][k] = 0.f;

    issue(0, 0);
    issue(1, 1);

    for (int kt = 0; kt < KT; kt++) {
        const int s = kt % 3;
        if (kt < KT - 1) CP_WAIT1(); else CP_WAIT0();
        __syncthreads();
        if (kt + 2 < KT) issue(kt + 2, (kt + 2) % 3);

        const uint32_t* AsU = (const uint32_t*)(smem + s * GSTG);
        const uint32_t* BsU = (const uint32_t*)(smem + s * GSTG + ASTG);

#pragma unroll
        for (int k8 = 0; k8 < 4; k8++) {
            uint32_t a[4][4], b[4][2];
#pragma unroll
            for (int mt = 0; mt < 4; mt++) {
                int r = wm + mt * 16 + gid;
                int c = k8 * 8 + tig;
                a[mt][0] = AsU[r * ASTRIDE + c];
                a[mt][1] = AsU[(r + 8) * ASTRIDE + c];
                a[mt][2] = AsU[r * ASTRIDE + c + 4];
                a[mt][3] = AsU[(r + 8) * ASTRIDE + c + 4];
            }
#pragma unroll
            for (int nt = 0; nt < 4; nt++) {
                int kr = k8 * 8 + tig;
                int cn = wn + nt * 8 + gid;
                b[nt][0] = BsU[kr * BSTRIDE + cn];
                b[nt][1] = BsU[(kr + 4) * BSTRIDE + cn];
            }
#pragma unroll
            for (int mt = 0; mt < 4; mt++)
#pragma unroll
                for (int nt = 0; nt < 4; nt++)
                    mma_tf32(acc[mt][nt], a[mt], b[nt]);
        }
    }

    const float gm = EPI ? gamma[0] : 0.f;
    const float* rp = EPI ? (resid + sC * blockIdx.z) : nullptr;
#pragma unroll
    for (int mt = 0; mt < 4; mt++) {
#pragma unroll
        for (int h = 0; h < 2; h++) {
            long long row = m0 + wm + mt * 16 + gid + h * 8;
#pragma unroll
            for (int nt = 0; nt < 4; nt++) {
                long long off = row * ldc + n0 + wn + nt * 8 + 2 * tig;
                float2 v = make_float2(acc[mt][nt][h * 2], acc[mt][nt][h * 2 + 1]);
                if (EPI) {
                    float2 rv = *reinterpret_cast<const float2*>(&rp[off]);
                    v.x = fmaf(gm, v.x, rv.x);
                    v.y = fmaf(gm, v.y, rv.y);
                }
                *reinterpret_cast<float2*>(&C[off]) = v;
            }
        }
    }
}

// ---------------------------------------------------------------------------
// Flash attention: per CTA 64 queries; loop 16 key-chunks of 64.
//   Q [64,64] from G slice of d_P, Kt [64,1024] = d_Ft, V [1024,256] = d_Hh
//   O accumulated in regs with online softmax; result -> d_O
// Warps: S phase 4m x 2n (warp 16x32); PV phase 4m x 2n over 256 (warp 16x128)
// Strides: 68 (=4 mod 32) for 64-wide tiles, 260 (=4 mod 32) for V.
// ---------------------------------------------------------------------------
#define QSTR 68
#define KSTR 68
#define PSTR 68
#define VSTR 260
#define NCHUNK 16
// float offsets in smem
#define SM_Q 0
#define SM_P (SM_Q + 64 * QSTR)
#define SM_K (SM_P + 64 * PSTR)          // 2 x 64*KSTR
#define SM_V (SM_K + 2 * 64 * KSTR)      // 2 x 64*VSTR
#define SM_RM (SM_V + 2 * 64 * VSTR)     // 2 x 64
#define SM_RS (SM_RM + 2 * 64)           // 2 x 64
#define FLASH_FLOATS (SM_RS + 2 * 64)
#define FLASH_SMEM (FLASH_FLOATS * 4)

__global__ void __launch_bounds__(256, 1) flash_kernel()
{
    extern __shared__ __align__(16) float fsm[];
    const uint32_t sb = smem_u32(fsm);

    const int b = blockIdx.y;
    const int q0 = blockIdx.x * 64;
    const float* Q = d_P + (long long)b * NPIX * NCAT + OFF_G;
    const float* Kt = d_Ft + (long long)b * C8 * NPOOL;
    const float* V = d_Hh + (long long)b * NPOOL * C2;
    float* O = d_O + (long long)b * NPIX * C2;

    const int tid = threadIdx.x;
    const int wid = tid >> 5, lane = tid & 31;
    const int gid = lane >> 2, tig = lane & 3;
    const int wm = (wid & 3) * 16;       // rows for both S and PV
    const int wnS = (wid >> 2) * 32;     // S cols
    const int wnP = (wid >> 2) * 128;    // PV cols

    auto issueK = [&](int c, int s) {
        const float* src = Kt + c * 64;
        uint32_t dst = sb + (uint32_t)((SM_K + s * 64 * KSTR) * 4);
#pragma unroll
        for (int it = 0; it < 4; it++) {
            int idx = tid + it * 256;
            int r = idx >> 4, c4 = idx & 15;
            cp16(dst + (uint32_t)((r * KSTR + c4 * 4) * 4),
                 src + (long long)r * NPOOL + c4 * 4);
        }
    };
    auto issueV = [&](int c, int s) {
        const float* src = V + (long long)(c * 64) * C2;
        uint32_t dst = sb + (uint32_t)((SM_V + s * 64 * VSTR) * 4);
#pragma unroll
        for (int it = 0; it < 16; it++) {
            int idx = tid + it * 256;
            int r = idx >> 6, c4 = idx & 63;
            cp16(dst + (uint32_t)((r * VSTR + c4 * 4) * 4),
                 src + (long long)r * C2 + c4 * 4);
        }
    };

    // prologue: Q + chunk 0 as group 0
    {
        uint32_t dq = sb + SM_Q * 4;
#pragma unroll
        for (int it = 0; it < 4; it++) {
            int idx = tid + it * 256;
            int r = idx >> 4, c4 = idx & 15;
            cp16(dq + (uint32_t)((r * QSTR + c4 * 4) * 4),
                 Q + (long long)(q0 + r) * NCAT + c4 * 4);
        }
        issueK(0, 0);
        issueV(0, 0);
        CP_COMMIT();
    }

    float accO[16][4];
#pragma unroll
    for (int i = 0; i < 16; i++)
#pragma unroll
        for (int j = 0; j < 4; j++) accO[i][j] = 0.f;
    float m_lo = -1e30f, m_hi = -1e30f, l_lo = 0.f, l_hi = 0.f;

    const uint32_t* Qu = (const uint32_t*)(fsm + SM_Q);
    float* Ps = fsm + SM_P;
    const uint32_t* Pu = (const uint32_t*)Ps;
    float* redm = fsm + SM_RM;
    float* reds = fsm + SM_RS;

    for (int c = 0; c < NCHUNK; c++) {
        const int s = c & 1;
        CP_WAIT0();
        __syncthreads();
        if (c + 1 < NCHUNK) { issueK(c + 1, s ^ 1); issueV(c + 1, s ^ 1); CP_COMMIT(); }

        const uint32_t* Ku = (const uint32_t*)(fsm + SM_K + s * 64 * KSTR);
        const uint32_t* Vu = (const uint32_t*)(fsm + SM_V + s * 64 * VSTR);

        // ---- S = Q @ Ktc : warp tile 16x32, accS[4 nt][4] ----
        float accS[4][4];
#pragma unroll
        for (int i = 0; i < 4; i++)
#pragma unroll
            for (int j = 0; j < 4; j++) accS[i][j] = 0.f;
#pragma unroll
        for (int k8 = 0; k8 < 8; k8++) {
            uint32_t a[4], bfr[4][2];
            int r = wm + gid, cc = k8 * 8 + tig;
            a[0] = Qu[r * QSTR + cc];
            a[1] = Qu[(r + 8) * QSTR + cc];
            a[2] = Qu[r * QSTR + cc + 4];
            a[3] = Qu[(r + 8) * QSTR + cc + 4];
#pragma unroll
            for (int nt = 0; nt < 4; nt++) {
                int kr = k8 * 8 + tig, cn = wnS + nt * 8 + gid;
                bfr[nt][0] = Ku[kr * KSTR + cn];
                bfr[nt][1] = Ku[(kr + 4) * KSTR + cn];
            }
#pragma unroll
            for (int nt = 0; nt < 4; nt++) mma_tf32(accS[nt], a, bfr[nt]);
        }

        // ---- chunk row max (within warp: over nt and tig lanes) ----
        float cm_lo = -1e30f, cm_hi = -1e30f;
#pragma unroll
        for (int nt = 0; nt < 4; nt++) {
            cm_lo = fmaxf(cm_lo, fmaxf(accS[nt][0], accS[nt][1]));
            cm_hi = fmaxf(cm_hi, fmaxf(accS[nt][2], accS[nt][3]));
        }
#pragma unroll
        for (int o = 1; o <= 2; o <<= 1) {
            cm_lo = fmaxf(cm_lo, __shfl_xor_sync(0xffffffffu, cm_lo, o));
            cm_hi = fmaxf(cm_hi, __shfl_xor_sync(0xffffffffu, cm_hi, o));
        }
        if (tig == 0) {
            redm[(wid >> 2) * 64 + wm + gid] = cm_lo;
            redm[(wid >> 2) * 64 + wm + gid + 8] = cm_hi;
        }
        __syncthreads();
        float mc_lo = fmaxf(redm[wm + gid], redm[64 + wm + gid]);
        float mc_hi = fmaxf(redm[wm + gid + 8], redm[64 + wm + gid + 8]);
        float mn_lo = fmaxf(m_lo, mc_lo);
        float mn_hi = fmaxf(m_hi, mc_hi);
        float sc_lo = __expf(m_lo - mn_lo);
        float sc_hi = __expf(m_hi - mn_hi);

        // ---- P = exp(S - m_new), store to smem, partial row sums ----
        float psum_lo = 0.f, psum_hi = 0.f;
#pragma unroll
        for (int nt = 0; nt < 4; nt++) {
            float e0 = __expf(accS[nt][0] - mn_lo);
            float e1 = __expf(accS[nt][1] - mn_lo);
            float e2 = __expf(accS[nt][2] - mn_hi);
            float e3 = __expf(accS[nt][3] - mn_hi);
            psum_lo += e0 + e1;
            psum_hi += e2 + e3;
            int col = wnS + nt * 8 + 2 * tig;
            *reinterpret_cast<float2*>(&Ps[(wm + gid) * PSTR + col]) = make_float2(e0, e1);
            *reinterpret_cast<float2*>(&Ps[(wm + gid + 8) * PSTR + col]) = make_float2(e2, e3);
        }
#pragma unroll
        for (int o = 1; o <= 2; o <<= 1) {
            psum_lo += __shfl_xor_sync(0xffffffffu, psum_lo, o);
            psum_hi += __shfl_xor_sync(0xffffffffu, psum_hi, o);
        }
        if (tig == 0) {
            reds[(wid >> 2) * 64 + wm + gid] = psum_lo;
            reds[(wid >> 2) * 64 + wm + gid + 8] = psum_hi;
        }
        __syncthreads();
        float su_lo = reds[wm + gid] + reds[64 + wm + gid];
        float su_hi = reds[wm + gid + 8] + reds[64 + wm + gid + 8];
        l_lo = l_lo * sc_lo + su_lo;
        l_hi = l_hi * sc_hi + su_hi;
        m_lo = mn_lo;
        m_hi = mn_hi;

        // ---- rescale O acc ----
#pragma unroll
        for (int nt = 0; nt < 16; nt++) {
            accO[nt][0] *= sc_lo;
            accO[nt][1] *= sc_lo;
            accO[nt][2] *= sc_hi;
            accO[nt][3] *= sc_hi;
        }

        // ---- O += P @ Vc : warp tile 16x128 ----
#pragma unroll
        for (int k8 = 0; k8 < 8; k8++) {
            uint32_t a[4];
            int r = wm + gid, cc = k8 * 8 + tig;
            a[0] = Pu[r * PSTR + cc];
            a[1] = Pu[(r + 8) * PSTR + cc];
            a[2] = Pu[r * PSTR + cc + 4];
            a[3] = Pu[(r + 8) * PSTR + cc + 4];
#pragma unroll
            for (int nt = 0; nt < 16; nt++) {
                uint32_t bfr[2];
                int kr = k8 * 8 + tig, cn = wnP + nt * 8 + gid;
                bfr[0] = Vu[kr * VSTR + cn];
                bfr[1] = Vu[(kr + 4) * VSTR + cn];
                mma_tf32(accO[nt], a, bfr);
            }
        }
    }

    // ---- finalize: O / l ----
    float inv_lo = 1.f / l_lo, inv_hi = 1.f / l_hi;
#pragma unroll
    for (int nt = 0; nt < 16; nt++) {
        int col = wnP + nt * 8 + 2 * tig;
        long long r_lo = (long long)(q0 + wm + gid) * C2 + col;
        long long r_hi = (long long)(q0 + wm + gid + 8) * C2 + col;
        *reinterpret_cast<float2*>(&O[r_lo]) =
            make_float2(accO[nt][0] * inv_lo, accO[nt][1] * inv_lo);
        *reinterpret_cast<float2*>(&O[r_hi]) =
            make_float2(accO[nt][2] * inv_hi, accO[nt][3] * inv_hi);
    }
}

// ---------------------------------------------------------------------------
// Concat wf|wg|wh -> Wcat [512, 384]
// ---------------------------------------------------------------------------
__global__ void concat_w_kernel(const float* __restrict__ wf,
                                const float* __restrict__ wg,
                                const float* __restrict__ wh)
{
    int idx = blockIdx.x * blockDim.x + threadIdx.x;
    if (idx >= CC * NCAT) return;
    int k = idx / NCAT;
    int j = idx % NCAT;
    float v;
    if (j < 64)       v = wf[k * C8 + j];
    else if (j < 128) v = wg[k * C8 + (j - 64)];
    else              v = wh[k * C2 + (j - 128)];
    d_Wcat[idx] = v;
}

// ---------------------------------------------------------------------------
// 2x2 max pool: f slice -> d_Ft [B, C8, NPOOL] (transposed), h -> d_Hh
// ---------------------------------------------------------------------------
__global__ void pool_kernel()
{
    int idx = blockIdx.x * blockDim.x + threadIdx.x;
    const int total = BATCH * NPOOL * (C8 + C2);
    if (idx >= total) return;
    int c = idx % (C8 + C2);
    int p = (idx / (C8 + C2)) % NPOOL;
    int b = idx / ((C8 + C2) * NPOOL);
    int ph = p >> 5;
    int pw = p & 31;
    int col = (c < C8) ? (OFF_F + c) : (OFF_H + (c - C8));
    const float* base = d_P + (long long)b * NPIX * NCAT;
    int r0 = (2 * ph) * WDIM + 2 * pw;
    float v0 = base[(long long)(r0) * NCAT + col];
    float v1 = base[(long long)(r0 + 1) * NCAT + col];
    float v2 = base[(long long)(r0 + WDIM) * NCAT + col];
    float v3 = base[(long long)(r0 + WDIM + 1) * NCAT + col];
    float v = fmaxf(fmaxf(v0, v1), fmaxf(v2, v3));
    if (c < C8) d_Ft[((long long)b * C8 + c) * NPOOL + p] = v;
    else        d_Hh[((long long)b * NPOOL + p) * C2 + (c - C8)] = v;
}

// ---------------------------------------------------------------------------
// Launch
// ---------------------------------------------------------------------------
extern "C" void kernel_launch(void* const* d_in, const int* in_sizes, int n_in,
                              void* d_out, int out_size)
{
    const float* x     = (const float*)d_in[0];
    const float* wf    = (const float*)d_in[1];
    const float* wg    = (const float*)d_in[2];
    const float* wh    = (const float*)d_in[3];
    const float* wo    = (const float*)d_in[4];
    const float* gamma = (const float*)d_in[5];
    float* out = (float*)d_out;

    float *pWcat, *pP, *pO;
    cudaGetSymbolAddress((void**)&pWcat, d_Wcat);
    cudaGetSymbolAddress((void**)&pP, d_P);
    cudaGetSymbolAddress((void**)&pO, d_O);

    cudaFuncSetAttribute(mma_gemm<false>,
                         cudaFuncAttributeMaxDynamicSharedMemorySize, SMEM_TOTAL);
    cudaFuncSetAttribute(mma_gemm<true>,
                         cudaFuncAttributeMaxDynamicSharedMemorySize, SMEM_TOTAL);
    cudaFuncSetAttribute(flash_kernel,
                         cudaFuncAttributeMaxDynamicSharedMemorySize, FLASH_SMEM);

    // 1) concat weights
    concat_w_kernel<<<(CC * NCAT + 255) / 256, 256>>>(wf, wg, wh);

    // 2) P = x @ Wcat   (M=32768, N=384, K=512)
    mma_gemm<false><<<dim3(NCAT / 64, (BATCH * NPIX) / 256, 1), 256, SMEM_TOTAL>>>(
        x, CC, 0, pWcat, NCAT, 0, pP, NCAT, 0, CC, nullptr, nullptr);

    // 3) pool -> Ft [B,64,1024] (transposed), H [B,1024,256]
    pool_kernel<<<(BATCH * NPOOL * (C8 + C2) + 255) / 256, 256>>>();

    // 4-6) fused attention: O = softmax(G @ Ft) @ H  -> d_O
    flash_kernel<<<dim3(NPIX / 64, BATCH), 256, FLASH_SMEM>>>();

    // 7) out = gamma * (O @ wo) + x  (M=32768, N=512, K=256)
    mma_gemm<true><<<dim3(CC / 64, (BATCH * NPIX) / 256, 1), 256, SMEM_TOTAL>>>(
        pO, C2, 0, wo, CC, 0, out, CC, 0, C2, x, gamma);
}

// round 5
// speedup vs baseline: 2.6027x; 1.0555x over previous
#include <cuda_runtime.h>
#include <cstdint>
#include <math.h>

// ---------------------------------------------------------------------------
// Problem constants
// ---------------------------------------------------------------------------
#define BATCH 8
#define WDIM 64
#define CC 512
#define C8 64
#define C2 256
#define NPIX 4096
#define NPOOL 1024
#define NCAT 384
#define OFF_F 0
#define OFF_G 64
#define OFF_H 128

// ---------------------------------------------------------------------------
// Scratch (device globals; allocation-free)
// ---------------------------------------------------------------------------
__device__ float d_Wcat[CC * NCAT];                     // 0.75 MB
__device__ float d_P[(long long)BATCH * NPIX * NCAT];   // 48 MB
__device__ float d_Ft[BATCH * C8 * NPOOL];              // 2 MB  pooled f, transposed [C8, NPOOL]
__device__ float d_Hh[BATCH * NPOOL * C2];              // 8 MB
__device__ float d_O[(long long)BATCH * NPIX * C2];     // 32 MB

// ---------------------------------------------------------------------------
// Helpers
// ---------------------------------------------------------------------------
__device__ __forceinline__ uint32_t smem_u32(const void* p) {
    uint32_t a;
    asm("{ .reg .u64 t; cvta.to.shared.u64 t, %1; cvt.u32.u64 %0, t; }" : "=r"(a) : "l"(p));
    return a;
}
__device__ __forceinline__ void cp16(uint32_t dst, const float* src) {
    asm volatile("cp.async.cg.shared.global [%0], [%1], 16;" ::"r"(dst), "l"(src));
}
#define CP_COMMIT() asm volatile("cp.async.commit_group;" ::: "memory")
#define CP_WAIT0()  asm volatile("cp.async.wait_group 0;" ::: "memory")
#define CP_WAIT1()  asm volatile("cp.async.wait_group 1;" ::: "memory")

__device__ __forceinline__ void mma_tf32(float* d, const uint32_t* a, const uint32_t* b) {
    asm volatile(
        "mma.sync.aligned.m16n8k8.row.col.f32.tf32.tf32.f32 "
        "{%0,%1,%2,%3}, {%4,%5,%6,%7}, {%8,%9}, {%0,%1,%2,%3};"
        : "+f"(d[0]), "+f"(d[1]), "+f"(d[2]), "+f"(d[3])
        : "r"(a[0]), "r"(a[1]), "r"(a[2]), "r"(a[3]), "r"(b[0]), "r"(b[1]));
}

// ---------------------------------------------------------------------------
// tf32 mma.sync GEMM: C[M,N] = A[M,K] * B[K,N]
// CTA tile 256x64, BK=32, 8 warps (4m x 2n), warp tile 64x32.
// 3-stage cp.async pipeline, issue-before-compute. EPI: C = gamma*acc + resid
// ---------------------------------------------------------------------------
#define ASTRIDE 36
#define BSTRIDE 72
#define ASTG (256 * ASTRIDE * 4)
#define BSTG (32 * BSTRIDE * 4)
#define GSTG (ASTG + BSTG)
#define SMEM_TOTAL (3 * GSTG)

template <bool EPI>
__global__ void __launch_bounds__(256, 1) mma_gemm(
    const float* __restrict__ A, int lda, long long sA,
    const float* __restrict__ B, int ldb, long long sB,
    float* __restrict__ C, int ldc, long long sC,
    int K, const float* __restrict__ resid, const float* __restrict__ gamma)
{
    extern __shared__ __align__(16) char smem[];
    A += sA * blockIdx.z;
    B += sB * blockIdx.z;
    C += sC * blockIdx.z;

    const int m0 = blockIdx.y * 256;
    const int n0 = blockIdx.x * 64;
    const int tid = threadIdx.x;
    const int wid = tid >> 5, lane = tid & 31;
    const int gid = lane >> 2, tig = lane & 3;
    const int wm = (wid & 3) * 64;
    const int wn = (wid >> 2) * 32;

    const uint32_t sb = smem_u32(smem);
    const int KT = K / 32;

    auto issue = [&](int kt, int s) {
        const uint32_t aB = sb + (uint32_t)(s * GSTG);
        const uint32_t bB = aB + ASTG;
        const float* Ap = A + (long long)m0 * lda + kt * 32;
#pragma unroll
        for (int it = 0; it < 8; it++) {
            int idx = tid + it * 256;
            int r = idx >> 3, kk = idx & 7;
            cp16(aB + (uint32_t)((r * ASTRIDE + kk * 4) * 4),
                 Ap + (long long)r * lda + kk * 4);
        }
        const float* Bp = B + (long long)(kt * 32) * ldb + n0;
#pragma unroll
        for (int it = 0; it < 2; it++) {
            int idx = tid + it * 256;
            int r = idx >> 4, c = idx & 15;
            cp16(bB + (uint32_t)((r * BSTRIDE + c * 4) * 4),
                 Bp + (long long)r * ldb + c * 4);
        }
        CP_COMMIT();
    };

    float acc[4][4][4];
#pragma unroll
    for (int i = 0; i < 4; i++)
#pragma unroll
        for (int j = 0; j < 4; j++)
#pragma unroll
            for (int k = 0; k < 4; k++) acc[i][j][k] = 0.f;

    issue(0, 0);
    issue(1, 1);

    for (int kt = 0; kt < KT; kt++) {
        const int s = kt % 3;
        if (kt < KT - 1) CP_WAIT1(); else CP_WAIT0();
        __syncthreads();
        if (kt + 2 < KT) issue(kt + 2, (kt + 2) % 3);

        const uint32_t* AsU = (const uint32_t*)(smem + s * GSTG);
        const uint32_t* BsU = (const uint32_t*)(smem + s * GSTG + ASTG);

#pragma unroll
        for (int k8 = 0; k8 < 4; k8++) {
            uint32_t a[4][4], b[4][2];
#pragma unroll
            for (int mt = 0; mt < 4; mt++) {
                int r = wm + mt * 16 + gid;
                int c = k8 * 8 + tig;
                a[mt][0] = AsU[r * ASTRIDE + c];
                a[mt][1] = AsU[(r + 8) * ASTRIDE + c];
                a[mt][2] = AsU[r * ASTRIDE + c + 4];
                a[mt][3] = AsU[(r + 8) * ASTRIDE + c + 4];
            }
#pragma unroll
            for (int nt = 0; nt < 4; nt++) {
                int kr = k8 * 8 + tig;
                int cn = wn + nt * 8 + gid;
                b[nt][0] = BsU[kr * BSTRIDE + cn];
                b[nt][1] = BsU[(kr + 4) * BSTRIDE + cn];
            }
#pragma unroll
            for (int mt = 0; mt < 4; mt++)
#pragma unroll
                for (int nt = 0; nt < 4; nt++)
                    mma_tf32(acc[mt][nt], a[mt], b[nt]);
        }
    }

    const float gm = EPI ? gamma[0] : 0.f;
    const float* rp = EPI ? (resid + sC * blockIdx.z) : nullptr;
#pragma unroll
    for (int mt = 0; mt < 4; mt++) {
#pragma unroll
        for (int h = 0; h < 2; h++) {
            long long row = m0 + wm + mt * 16 + gid + h * 8;
#pragma unroll
            for (int nt = 0; nt < 4; nt++) {
                long long off = row * ldc + n0 + wn + nt * 8 + 2 * tig;
                float2 v = make_float2(acc[mt][nt][h * 2], acc[mt][nt][h * 2 + 1]);
                if (EPI) {
                    float2 rv = *reinterpret_cast<const float2*>(&rp[off]);
                    v.x = fmaf(gm, v.x, rv.x);
                    v.y = fmaf(gm, v.y, rv.y);
                }
                *reinterpret_cast<float2*>(&C[off]) = v;
            }
        }
    }
}

// ---------------------------------------------------------------------------
// Flash attention: 512 threads (16 warps), 128 queries/CTA, 16 key-chunks of 64.
//   Q [128,64] (G slice of d_P), Kt [64,1024] = d_Ft, V [1024,256] = d_Hh
// Single-buffered K and V:
//   chunk c: waitK -> S = Q@Kc -> sync -> issue K(c+1) -> softmax update
//            -> waitV -> sync -> O += P@Vc -> sync -> issue V(c+1)
// Warps: 8m x 2n. S warp tile 16x32; PV warp tile 16x128.
// ---------------------------------------------------------------------------
#define QSTR 68
#define KSTR 68
#define PSTR 68
#define VSTR 260
#define NCHUNK 16
#define FQ 128
// float offsets in smem
#define SM_Q 0
#define SM_P (SM_Q + FQ * QSTR)
#define SM_K (SM_P + FQ * PSTR)
#define SM_V (SM_K + 64 * KSTR)
#define SM_RM (SM_V + 64 * VSTR)         // 2 x 128
#define SM_RS (SM_RM + 2 * FQ)           // 2 x 128
#define FLASH_FLOATS (SM_RS + 2 * FQ)
#define FLASH_SMEM (FLASH_FLOATS * 4)

__global__ void __launch_bounds__(512, 1) flash_kernel()
{
    extern __shared__ __align__(16) float fsm[];
    const uint32_t sb = smem_u32(fsm);

    const int b = blockIdx.y;
    const int q0 = blockIdx.x * FQ;
    const float* Q = d_P + (long long)b * NPIX * NCAT + OFF_G;
    const float* Kt = d_Ft + (long long)b * C8 * NPOOL;
    const float* V = d_Hh + (long long)b * NPOOL * C2;
    float* O = d_O + (long long)b * NPIX * C2;

    const int tid = threadIdx.x;
    const int wid = tid >> 5, lane = tid & 31;
    const int gid = lane >> 2, tig = lane & 3;
    const int wm = (wid & 7) * 16;       // 8 m-groups
    const int wgrp = wid >> 3;           // 2 n-groups
    const int wnS = wgrp * 32;
    const int wnP = wgrp * 128;

    auto issueK = [&](int c) {
        const float* src = Kt + c * 64;
        uint32_t dst = sb + (uint32_t)(SM_K * 4);
#pragma unroll
        for (int it = 0; it < 2; it++) {
            int idx = tid + it * 512;
            int r = idx >> 4, c4 = idx & 15;
            cp16(dst + (uint32_t)((r * KSTR + c4 * 4) * 4),
                 src + (long long)r * NPOOL + c4 * 4);
        }
        CP_COMMIT();
    };
    auto issueV = [&](int c) {
        const float* src = V + (long long)(c * 64) * C2;
        uint32_t dst = sb + (uint32_t)(SM_V * 4);
#pragma unroll
        for (int it = 0; it < 8; it++) {
            int idx = tid + it * 512;
            int r = idx >> 6, c4 = idx & 63;
            cp16(dst + (uint32_t)((r * VSTR + c4 * 4) * 4),
                 src + (long long)r * C2 + c4 * 4);
        }
        CP_COMMIT();
    };

    // prologue: Q + K0 (group), V0 (group)
    {
        uint32_t dq = sb + SM_Q * 4;
#pragma unroll
        for (int it = 0; it < 4; it++) {
            int idx = tid + it * 512;
            int r = idx >> 4, c4 = idx & 15;
            cp16(dq + (uint32_t)((r * QSTR + c4 * 4) * 4),
                 Q + (long long)(q0 + r) * NCAT + c4 * 4);
        }
        issueK(0);   // commits Q+K0 together
        issueV(0);
    }

    float accO[16][4];
#pragma unroll
    for (int i = 0; i < 16; i++)
#pragma unroll
        for (int j = 0; j < 4; j++) accO[i][j] = 0.f;
    float m_lo = -1e30f, m_hi = -1e30f, l_lo = 0.f, l_hi = 0.f;

    const uint32_t* Qu = (const uint32_t*)(fsm + SM_Q);
    float* Ps = fsm + SM_P;
    const uint32_t* Pu = (const uint32_t*)Ps;
    const uint32_t* Ku = (const uint32_t*)(fsm + SM_K);
    const uint32_t* Vu = (const uint32_t*)(fsm + SM_V);
    float* redm = fsm + SM_RM;
    float* reds = fsm + SM_RS;

    for (int c = 0; c < NCHUNK; c++) {
        // wait K(c) (V(c) may still be in flight)
        CP_WAIT1();
        __syncthreads();

        // ---- S = Q @ Kc : warp tile 16x32 ----
        float accS[4][4];
#pragma unroll
        for (int i = 0; i < 4; i++)
#pragma unroll
            for (int j = 0; j < 4; j++) accS[i][j] = 0.f;
#pragma unroll
        for (int k8 = 0; k8 < 8; k8++) {
            uint32_t a[4], bfr[4][2];
            int r = wm + gid, cc = k8 * 8 + tig;
            a[0] = Qu[r * QSTR + cc];
            a[1] = Qu[(r + 8) * QSTR + cc];
            a[2] = Qu[r * QSTR + cc + 4];
            a[3] = Qu[(r + 8) * QSTR + cc + 4];
#pragma unroll
            for (int nt = 0; nt < 4; nt++) {
                int kr = k8 * 8 + tig, cn = wnS + nt * 8 + gid;
                bfr[nt][0] = Ku[kr * KSTR + cn];
                bfr[nt][1] = Ku[(kr + 4) * KSTR + cn];
            }
#pragma unroll
            for (int nt = 0; nt < 4; nt++) mma_tf32(accS[nt], a, bfr[nt]);
        }

        // ---- chunk row max ----
        float cm_lo = -1e30f, cm_hi = -1e30f;
#pragma unroll
        for (int nt = 0; nt < 4; nt++) {
            cm_lo = fmaxf(cm_lo, fmaxf(accS[nt][0], accS[nt][1]));
            cm_hi = fmaxf(cm_hi, fmaxf(accS[nt][2], accS[nt][3]));
        }
#pragma unroll
        for (int o = 1; o <= 2; o <<= 1) {
            cm_lo = fmaxf(cm_lo, __shfl_xor_sync(0xffffffffu, cm_lo, o));
            cm_hi = fmaxf(cm_hi, __shfl_xor_sync(0xffffffffu, cm_hi, o));
        }
        if (tig == 0) {
            redm[wgrp * FQ + wm + gid] = cm_lo;
            redm[wgrp * FQ + wm + gid + 8] = cm_hi;
        }
        __syncthreads();       // S-phase done: K buffer free
        if (c + 1 < NCHUNK) issueK(c + 1);

        float mc_lo = fmaxf(redm[wm + gid], redm[FQ + wm + gid]);
        float mc_hi = fmaxf(redm[wm + gid + 8], redm[FQ + wm + gid + 8]);
        float mn_lo = fmaxf(m_lo, mc_lo);
        float mn_hi = fmaxf(m_hi, mc_hi);
        float sc_lo = __expf(m_lo - mn_lo);
        float sc_hi = __expf(m_hi - mn_hi);

        // ---- P = exp(S - m_new) -> smem; partial row sums ----
        float psum_lo = 0.f, psum_hi = 0.f;
#pragma unroll
        for (int nt = 0; nt < 4; nt++) {
            float e0 = __expf(accS[nt][0] - mn_lo);
            float e1 = __expf(accS[nt][1] - mn_lo);
            float e2 = __expf(accS[nt][2] - mn_hi);
            float e3 = __expf(accS[nt][3] - mn_hi);
            psum_lo += e0 + e1;
            psum_hi += e2 + e3;
            int col = wnS + nt * 8 + 2 * tig;
            *reinterpret_cast<float2*>(&Ps[(wm + gid) * PSTR + col]) = make_float2(e0, e1);
            *reinterpret_cast<float2*>(&Ps[(wm + gid + 8) * PSTR + col]) = make_float2(e2, e3);
        }
#pragma unroll
        for (int o = 1; o <= 2; o <<= 1) {
            psum_lo += __shfl_xor_sync(0xffffffffu, psum_lo, o);
            psum_hi += __shfl_xor_sync(0xffffffffu, psum_hi, o);
        }
        if (tig == 0) {
            reds[wgrp * FQ + wm + gid] = psum_lo;
            reds[wgrp * FQ + wm + gid + 8] = psum_hi;
        }
        __syncthreads();
        float su_lo = reds[wm + gid] + reds[FQ + wm + gid];
        float su_hi = reds[wm + gid + 8] + reds[FQ + wm + gid + 8];
        l_lo = l_lo * sc_lo + su_lo;
        l_hi = l_hi * sc_hi + su_hi;
        m_lo = mn_lo;
        m_hi = mn_hi;

        // ---- rescale O acc ----
#pragma unroll
        for (int nt = 0; nt < 16; nt++) {
            accO[nt][0] *= sc_lo;
            accO[nt][1] *= sc_lo;
            accO[nt][2] *= sc_hi;
            accO[nt][3] *= sc_hi;
        }

        // wait V(c) (K(c+1) may still be in flight)
        if (c + 1 < NCHUNK) CP_WAIT1(); else CP_WAIT0();
        __syncthreads();

        // ---- O += P @ Vc : warp tile 16x128 ----
#pragma unroll
        for (int k8 = 0; k8 < 8; k8++) {
            uint32_t a[4];
            int r = wm + gid, cc = k8 * 8 + tig;
            a[0] = Pu[r * PSTR + cc];
            a[1] = Pu[(r + 8) * PSTR + cc];
            a[2] = Pu[r * PSTR + cc + 4];
            a[3] = Pu[(r + 8) * PSTR + cc + 4];
#pragma unroll
            for (int nt = 0; nt < 16; nt++) {
                uint32_t bfr[2];
                int kr = k8 * 8 + tig, cn = wnP + nt * 8 + gid;
                bfr[0] = Vu[kr * VSTR + cn];
                bfr[1] = Vu[(kr + 4) * VSTR + cn];
                mma_tf32(accO[nt], a, bfr);
            }
        }
        __syncthreads();       // PV done: V buffer free
        if (c + 1 < NCHUNK) issueV(c + 1);
    }

    // ---- finalize: O / l ----
    float inv_lo = 1.f / l_lo, inv_hi = 1.f / l_hi;
#pragma unroll
    for (int nt = 0; nt < 16; nt++) {
        int col = wnP + nt * 8 + 2 * tig;
        long long r_lo = (long long)(q0 + wm + gid) * C2 + col;
        long long r_hi = (long long)(q0 + wm + gid + 8) * C2 + col;
        *reinterpret_cast<float2*>(&O[r_lo]) =
            make_float2(accO[nt][0] * inv_lo, accO[nt][1] * inv_lo);
        *reinterpret_cast<float2*>(&O[r_hi]) =
            make_float2(accO[nt][2] * inv_hi, accO[nt][3] * inv_hi);
    }
}

// ---------------------------------------------------------------------------
// Concat wf|wg|wh -> Wcat [512, 384]
// ---------------------------------------------------------------------------
__global__ void concat_w_kernel(const float* __restrict__ wf,
                                const float* __restrict__ wg,
                                const float* __restrict__ wh)
{
    int idx = blockIdx.x * blockDim.x + threadIdx.x;
    if (idx >= CC * NCAT) return;
    int k = idx / NCAT;
    int j = idx % NCAT;
    float v;
    if (j < 64)       v = wf[k * C8 + j];
    else if (j < 128) v = wg[k * C8 + (j - 64)];
    else              v = wh[k * C2 + (j - 128)];
    d_Wcat[idx] = v;
}

// ---------------------------------------------------------------------------
// 2x2 max pool: f slice -> d_Ft [B, C8, NPOOL] (transposed), h -> d_Hh
// ---------------------------------------------------------------------------
__global__ void pool_kernel()
{
    int idx = blockIdx.x * blockDim.x + threadIdx.x;
    const int total = BATCH * NPOOL * (C8 + C2);
    if (idx >= total) return;
    int c = idx % (C8 + C2);
    int p = (idx / (C8 + C2)) % NPOOL;
    int b = idx / ((C8 + C2) * NPOOL);
    int ph = p >> 5;
    int pw = p & 31;
    int col = (c < C8) ? (OFF_F + c) : (OFF_H + (c - C8));
    const float* base = d_P + (long long)b * NPIX * NCAT;
    int r0 = (2 * ph) * WDIM + 2 * pw;
    float v0 = base[(long long)(r0) * NCAT + col];
    float v1 = base[(long long)(r0 + 1) * NCAT + col];
    float v2 = base[(long long)(r0 + WDIM) * NCAT + col];
    float v3 = base[(long long)(r0 + WDIM + 1) * NCAT + col];
    float v = fmaxf(fmaxf(v0, v1), fmaxf(v2, v3));
    if (c < C8) d_Ft[((long long)b * C8 + c) * NPOOL + p] = v;
    else        d_Hh[((long long)b * NPOOL + p) * C2 + (c - C8)] = v;
}

// ---------------------------------------------------------------------------
// Launch
// ---------------------------------------------------------------------------
extern "C" void kernel_launch(void* const* d_in, const int* in_sizes, int n_in,
                              void* d_out, int out_size)
{
    const float* x     = (const float*)d_in[0];
    const float* wf    = (const float*)d_in[1];
    const float* wg    = (const float*)d_in[2];
    const float* wh    = (const float*)d_in[3];
    const float* wo    = (const float*)d_in[4];
    const float* gamma = (const float*)d_in[5];
    float* out = (float*)d_out;

    float *pWcat, *pP, *pO;
    cudaGetSymbolAddress((void**)&pWcat, d_Wcat);
    cudaGetSymbolAddress((void**)&pP, d_P);
    cudaGetSymbolAddress((void**)&pO, d_O);

    cudaFuncSetAttribute(mma_gemm<false>,
                         cudaFuncAttributeMaxDynamicSharedMemorySize, SMEM_TOTAL);
    cudaFuncSetAttribute(mma_gemm<true>,
                         cudaFuncAttributeMaxDynamicSharedMemorySize, SMEM_TOTAL);
    cudaFuncSetAttribute(flash_kernel,
                         cudaFuncAttributeMaxDynamicSharedMemorySize, FLASH_SMEM);

    // 1) concat weights
    concat_w_kernel<<<(CC * NCAT + 255) / 256, 256>>>(wf, wg, wh);

    // 2) P = x @ Wcat   (M=32768, N=384, K=512)
    mma_gemm<false><<<dim3(NCAT / 64, (BATCH * NPIX) / 256, 1), 256, SMEM_TOTAL>>>(
        x, CC, 0, pWcat, NCAT, 0, pP, NCAT, 0, CC, nullptr, nullptr);

    // 3) pool -> Ft [B,64,1024] (transposed), H [B,1024,256]
    pool_kernel<<<(BATCH * NPOOL * (C8 + C2) + 255) / 256, 256>>>();

    // 4-6) fused attention: O = softmax(G @ Ft) @ H  -> d_O
    flash_kernel<<<dim3(NPIX / FQ, BATCH), 512, FLASH_SMEM>>>();

    // 7) out = gamma * (O @ wo) + x  (M=32768, N=512, K=256)
    mma_gemm<true><<<dim3(CC / 64, (BATCH * NPIX) / 256, 1), 256, SMEM_TOTAL>>>(
        pO, C2, 0, wo, CC, 0, out, CC, 0, C2, x, gamma);
}

// round 6
// speedup vs baseline: 4.6272x; 1.7778x over previous
#include <cuda_runtime.h>
#include <cuda_fp16.h>
#include <cstdint>
#include <math.h>

// ---------------------------------------------------------------------------
// Problem constants
// ---------------------------------------------------------------------------
#define BATCH 8
#define WDIM 64
#define CC 512
#define C8 64
#define C2 256
#define NPIX 4096
#define NPOOL 1024
#define NCAT 384
#define OFF_F 0
#define OFF_G 64
#define OFF_H 128

// ---------------------------------------------------------------------------
// Scratch (device globals; allocation-free)
// ---------------------------------------------------------------------------
__device__ __half d_Xh[(long long)BATCH * NPIX * CC];     // 32 MB  x in fp16
__device__ __half d_WcatT[NCAT * CC];                     // [384][512] fp16
__device__ __half d_WoT[CC * C2];                         // [512][256] fp16
__device__ __half d_Ph[(long long)BATCH * NPIX * NCAT];   // 24 MB  [f|g|h] fp16
__device__ __half d_Fh[BATCH * NPOOL * C8];               // 1 MB   pooled f [p][c]
__device__ __half d_Vth[BATCH * C2 * NPOOL];              // 4 MB   pooled h transposed [d][p]
__device__ __half d_Oh[(long long)BATCH * NPIX * C2];     // 16 MB  attention out fp16

// ---------------------------------------------------------------------------
// Helpers
// ---------------------------------------------------------------------------
__device__ __forceinline__ uint32_t smem_u32(const void* p) {
    uint32_t a;
    asm("{ .reg .u64 t; cvta.to.shared.u64 t, %1; cvt.u32.u64 %0, t; }" : "=r"(a) : "l"(p));
    return a;
}
__device__ __forceinline__ void cp16(uint32_t dst, const void* src) {
    asm volatile("cp.async.cg.shared.global [%0], [%1], 16;" ::"r"(dst), "l"(src));
}
#define CP_COMMIT() asm volatile("cp.async.commit_group;" ::: "memory")
#define CP_WAIT0()  asm volatile("cp.async.wait_group 0;" ::: "memory")
#define CP_WAIT1()  asm volatile("cp.async.wait_group 1;" ::: "memory")

__device__ __forceinline__ void mma_f16(float* d, const uint32_t* a, const uint32_t* b) {
    asm volatile(
        "mma.sync.aligned.m16n8k16.row.col.f32.f16.f16.f32 "
        "{%0,%1,%2,%3}, {%4,%5,%6,%7}, {%8,%9}, {%0,%1,%2,%3};"
        : "+f"(d[0]), "+f"(d[1]), "+f"(d[2]), "+f"(d[3])
        : "r"(a[0]), "r"(a[1]), "r"(a[2]), "r"(a[3]), "r"(b[0]), "r"(b[1]));
}
__device__ __forceinline__ uint32_t pack2(float x, float y) {
    __half2 h = __floats2half2_rn(x, y);
    return *reinterpret_cast<uint32_t*>(&h);
}

// ---------------------------------------------------------------------------
// fp16 mma.sync GEMM:  C[M,N] = A[M,K] * Bt[N,K]^T
// CTA 256x64, BK=32 halfs, 8 warps (4m x 2n), 3-stage cp.async pipeline.
// EPI=false: C fp16.   EPI=true: C = gamma*acc + resid (fp32).
// Strides: 40 halfs = 20 words (20g+t banks all distinct).
// ---------------------------------------------------------------------------
#define HSTR 40
#define HASTG (256 * HSTR * 2)
#define HBSTG (64 * HSTR * 2)
#define HGSTG (HASTG + HBSTG)
#define SMEM_TOTAL_G (3 * HGSTG)

template <bool EPI>
__global__ void __launch_bounds__(256, 2) mma_gemm_h(
    const __half* __restrict__ A, int lda,
    const __half* __restrict__ Bt, int ldb,
    void* __restrict__ Cv, int ldc,
    int K, const float* __restrict__ resid, const float* __restrict__ gamma)
{
    extern __shared__ __align__(16) char smem[];
    const int m0 = blockIdx.y * 256;
    const int n0 = blockIdx.x * 64;
    const int tid = threadIdx.x;
    const int wid = tid >> 5, lane = tid & 31;
    const int gid = lane >> 2, tig = lane & 3;
    const int wm = (wid & 3) * 64;
    const int wn = (wid >> 2) * 32;

    const uint32_t sb = smem_u32(smem);
    const int KT = K / 32;

    auto issue = [&](int kt, int s) {
        const uint32_t aB = sb + (uint32_t)(s * HGSTG);
        const uint32_t bB = aB + HASTG;
#pragma unroll
        for (int it = 0; it < 4; it++) {
            int idx = tid + it * 256;
            int r = idx >> 2, q = idx & 3;
            cp16(aB + (uint32_t)(r * 80 + q * 16),
                 A + (long long)(m0 + r) * lda + kt * 32 + q * 8);
        }
        {
            int r = tid >> 2, q = tid & 3;
            cp16(bB + (uint32_t)(r * 80 + q * 16),
                 Bt + (long long)(n0 + r) * ldb + kt * 32 + q * 8);
        }
        CP_COMMIT();
    };

    float acc[4][4][4];
#pragma unroll
    for (int i = 0; i < 4; i++)
#pragma unroll
        for (int j = 0; j < 4; j++)
#pragma unroll
            for (int k = 0; k < 4; k++) acc[i][j][k] = 0.f;

    issue(0, 0);
    issue(1, 1);

    for (int kt = 0; kt < KT; kt++) {
        const int s = kt % 3;
        if (kt < KT - 1) CP_WAIT1(); else CP_WAIT0();
        __syncthreads();
        if (kt + 2 < KT) issue(kt + 2, (kt + 2) % 3);

        const uint32_t* AsU = (const uint32_t*)(smem + s * HGSTG);
        const uint32_t* BsU = (const uint32_t*)(smem + s * HGSTG + HASTG);

#pragma unroll
        for (int ks = 0; ks < 2; ks++) {
            uint32_t a[4][4], b[4][2];
#pragma unroll
            for (int mt = 0; mt < 4; mt++) {
                int w = (wm + mt * 16 + gid) * 20 + ks * 8 + tig;
                a[mt][0] = AsU[w];
                a[mt][1] = AsU[w + 8 * 20];
                a[mt][2] = AsU[w + 4];
                a[mt][3] = AsU[w + 8 * 20 + 4];
            }
#pragma unroll
            for (int nt = 0; nt < 4; nt++) {
                int w = (wn + nt * 8 + gid) * 20 + ks * 8 + tig;
                b[nt][0] = BsU[w];
                b[nt][1] = BsU[w + 4];
            }
#pragma unroll
            for (int mt = 0; mt < 4; mt++)
#pragma unroll
                for (int nt = 0; nt < 4; nt++)
                    mma_f16(acc[mt][nt], a[mt], b[nt]);
        }
    }

    if (EPI) {
        float* C = (float*)Cv;
        const float gm = gamma[0];
#pragma unroll
        for (int mt = 0; mt < 4; mt++)
#pragma unroll
            for (int h = 0; h < 2; h++) {
                long long row = m0 + wm + mt * 16 + gid + h * 8;
#pragma unroll
                for (int nt = 0; nt < 4; nt++) {
                    long long off = row * ldc + n0 + wn + nt * 8 + 2 * tig;
                    float2 rv = *reinterpret_cast<const float2*>(&resid[off]);
                    float2 v;
                    v.x = fmaf(gm, acc[mt][nt][h * 2], rv.x);
                    v.y = fmaf(gm, acc[mt][nt][h * 2 + 1], rv.y);
                    *reinterpret_cast<float2*>(&C[off]) = v;
                }
            }
    } else {
        __half* C = (__half*)Cv;
#pragma unroll
        for (int mt = 0; mt < 4; mt++)
#pragma unroll
            for (int h = 0; h < 2; h++) {
                long long row = m0 + wm + mt * 16 + gid + h * 8;
#pragma unroll
                for (int nt = 0; nt < 4; nt++) {
                    long long off = row * ldc + n0 + wn + nt * 8 + 2 * tig;
                    uint32_t u = pack2(acc[mt][nt][h * 2], acc[mt][nt][h * 2 + 1]);
                    *reinterpret_cast<uint32_t*>(&C[off]) = u;
                }
            }
    }
}

// ---------------------------------------------------------------------------
// Flash attention (fp16 operands, fp32 acc): 512 thr, 128 q/CTA, 16 chunks of 64.
// Warps 4m x 4n; per warp 2 m-tiles (32 rows). Single-buffer K/V staged issue.
// Smem rows: 72 halfs = 36 words (4g+t bank pattern, conflict-free).
// ---------------------------------------------------------------------------
#define FQ 128
#define NCHUNK 16
// byte offsets
#define SM_Q 0
#define SM_P 18432
#define SM_K 36864
#define SM_V 46080
#define SM_RM 82944
#define SM_RS 84992
#define FLASH_SMEM 87040

__global__ void __launch_bounds__(512, 1) flash_h()
{
    extern __shared__ __align__(16) char fsm[];
    const uint32_t sb = smem_u32(fsm);

    const int b = blockIdx.y;
    const int q0 = blockIdx.x * FQ;
    const __half* Qg = d_Ph + (long long)b * NPIX * NCAT + OFF_G;
    const __half* Fb = d_Fh + b * NPOOL * C8;
    const __half* Vtb = d_Vth + (long long)b * C2 * NPOOL;
    __half* Ob = d_Oh + (long long)b * NPIX * C2;

    const int tid = threadIdx.x;
    const int wid = tid >> 5, lane = tid & 31;
    const int gid = lane >> 2, tig = lane & 3;
    const int wm = (wid & 3) * 32;
    const int wgrp = wid >> 2;
    const int wnS = wgrp * 16;
    const int wnP = wgrp * 64;

    auto issueK = [&](int c) {
        int r = tid >> 3, q = tid & 7;
        cp16(sb + SM_K + (uint32_t)(r * 144 + q * 16),
             Fb + (c * 64 + r) * C8 + q * 8);
        CP_COMMIT();
    };
    auto issueV = [&](int c) {
#pragma unroll
        for (int it = 0; it < 4; it++) {
            int idx = tid + it * 512;
            int r = idx >> 3, q = idx & 7;
            cp16(sb + SM_V + (uint32_t)(r * 144 + q * 16),
                 Vtb + (long long)r * NPOOL + c * 64 + q * 8);
        }
        CP_COMMIT();
    };

    // prologue: Q + K0 one group, V0 another
    {
#pragma unroll
        for (int it = 0; it < 2; it++) {
            int idx = tid + it * 512;
            int r = idx >> 3, q = idx & 7;
            cp16(sb + SM_Q + (uint32_t)(r * 144 + q * 16),
                 Qg + (long long)(q0 + r) * NCAT + q * 8);
        }
        issueK(0);
        issueV(0);
    }

    float accO[2][8][4];
#pragma unroll
    for (int m = 0; m < 2; m++)
#pragma unroll
        for (int n = 0; n < 8; n++)
#pragma unroll
            for (int k = 0; k < 4; k++) accO[m][n][k] = 0.f;
    float mM[2][2] = {{-1e30f, -1e30f}, {-1e30f, -1e30f}};
    float lL[2][2] = {{0.f, 0.f}, {0.f, 0.f}};

    const uint32_t* Qw = (const uint32_t*)(fsm + SM_Q);
    const uint32_t* Kw = (const uint32_t*)(fsm + SM_K);
    const uint32_t* Vw = (const uint32_t*)(fsm + SM_V);
    uint32_t* Pw = (uint32_t*)(fsm + SM_P);
    float* redm = (float*)(fsm + SM_RM);
    float* reds = (float*)(fsm + SM_RS);

    for (int c = 0; c < NCHUNK; c++) {
        CP_WAIT1();                    // K(c) ready (V(c) may pend)
        __syncthreads();

        // ---- S = Q @ F^T : accS[mt][nt][4] ----
        float accS[2][2][4];
#pragma unroll
        for (int m = 0; m < 2; m++)
#pragma unroll
            for (int n = 0; n < 2; n++)
#pragma unroll
                for (int k = 0; k < 4; k++) accS[m][n][k] = 0.f;
#pragma unroll
        for (int ks = 0; ks < 4; ks++) {
            uint32_t a[2][4], bb[2][2];
#pragma unroll
            for (int mt = 0; mt < 2; mt++) {
                int w = (wm + mt * 16 + gid) * 36 + ks * 8 + tig;
                a[mt][0] = Qw[w];
                a[mt][1] = Qw[w + 8 * 36];
                a[mt][2] = Qw[w + 4];
                a[mt][3] = Qw[w + 8 * 36 + 4];
            }
#pragma unroll
            for (int nt = 0; nt < 2; nt++) {
                int w = (wnS + nt * 8 + gid) * 36 + ks * 8 + tig;
                bb[nt][0] = Kw[w];
                bb[nt][1] = Kw[w + 4];
            }
#pragma unroll
            for (int mt = 0; mt < 2; mt++)
#pragma unroll
                for (int nt = 0; nt < 2; nt++)
                    mma_f16(accS[mt][nt], a[mt], bb[nt]);
        }

        // ---- chunk row max ----
#pragma unroll
        for (int mt = 0; mt < 2; mt++) {
            float cl = fmaxf(fmaxf(accS[mt][0][0], accS[mt][0][1]),
                             fmaxf(accS[mt][1][0], accS[mt][1][1]));
            float ch = fmaxf(fmaxf(accS[mt][0][2], accS[mt][0][3]),
                             fmaxf(accS[mt][1][2], accS[mt][1][3]));
#pragma unroll
            for (int o = 1; o <= 2; o <<= 1) {
                cl = fmaxf(cl, __shfl_xor_sync(0xffffffffu, cl, o));
                ch = fmaxf(ch, __shfl_xor_sync(0xffffffffu, ch, o));
            }
            if (tig == 0) {
                redm[wgrp * FQ + wm + mt * 16 + gid] = cl;
                redm[wgrp * FQ + wm + mt * 16 + gid + 8] = ch;
            }
        }
        __syncthreads();               // S done: K buffer free
        if (c + 1 < NCHUNK) issueK(c + 1);

        float sc[2][2];
#pragma unroll
        for (int mt = 0; mt < 2; mt++)
#pragma unroll
            for (int h = 0; h < 2; h++) {
                int row = wm + mt * 16 + gid + h * 8;
                float mc = fmaxf(fmaxf(redm[row], redm[FQ + row]),
                                 fmaxf(redm[2 * FQ + row], redm[3 * FQ + row]));
                float mn = fmaxf(mM[mt][h], mc);
                sc[mt][h] = __expf(mM[mt][h] - mn);
                mM[mt][h] = mn;
            }

        // ---- P = exp(S - m) -> smem fp16; partial sums ----
        float ps[2][2] = {{0.f, 0.f}, {0.f, 0.f}};
#pragma unroll
        for (int mt = 0; mt < 2; mt++) {
            int row = wm + mt * 16 + gid;
#pragma unroll
            for (int nt = 0; nt < 2; nt++) {
                float e0 = __expf(accS[mt][nt][0] - mM[mt][0]);
                float e1 = __expf(accS[mt][nt][1] - mM[mt][0]);
                float e2 = __expf(accS[mt][nt][2] - mM[mt][1]);
                float e3 = __expf(accS[mt][nt][3] - mM[mt][1]);
                ps[mt][0] += e0 + e1;
                ps[mt][1] += e2 + e3;
                int w = row * 36 + wgrp * 8 + nt * 4 + tig;
                Pw[w] = pack2(e0, e1);
                Pw[w + 8 * 36] = pack2(e2, e3);
            }
        }
#pragma unroll
        for (int mt = 0; mt < 2; mt++) {
#pragma unroll
            for (int o = 1; o <= 2; o <<= 1) {
                ps[mt][0] += __shfl_xor_sync(0xffffffffu, ps[mt][0], o);
                ps[mt][1] += __shfl_xor_sync(0xffffffffu, ps[mt][1], o);
            }
            if (tig == 0) {
                reds[wgrp * FQ + wm + mt * 16 + gid] = ps[mt][0];
                reds[wgrp * FQ + wm + mt * 16 + gid + 8] = ps[mt][1];
            }
        }
        __syncthreads();
#pragma unroll
        for (int mt = 0; mt < 2; mt++)
#pragma unroll
            for (int h = 0; h < 2; h++) {
                int row = wm + mt * 16 + gid + h * 8;
                float su = reds[row] + reds[FQ + row] +
                           reds[2 * FQ + row] + reds[3 * FQ + row];
                lL[mt][h] = lL[mt][h] * sc[mt][h] + su;
            }

        // ---- rescale O ----
#pragma unroll
        for (int mt = 0; mt < 2; mt++)
#pragma unroll
            for (int nt = 0; nt < 8; nt++) {
                accO[mt][nt][0] *= sc[mt][0];
                accO[mt][nt][1] *= sc[mt][0];
                accO[mt][nt][2] *= sc[mt][1];
                accO[mt][nt][3] *= sc[mt][1];
            }

        // ---- wait V(c) ----
        if (c + 1 < NCHUNK) CP_WAIT1(); else CP_WAIT0();
        __syncthreads();

        // ---- O += P @ V ----
#pragma unroll
        for (int ks = 0; ks < 4; ks++) {
            uint32_t a[2][4];
#pragma unroll
            for (int mt = 0; mt < 2; mt++) {
                int w = (wm + mt * 16 + gid) * 36 + ks * 8 + tig;
                a[mt][0] = Pw[w];
                a[mt][1] = Pw[w + 8 * 36];
                a[mt][2] = Pw[w + 4];
                a[mt][3] = Pw[w + 8 * 36 + 4];
            }
#pragma unroll
            for (int nt = 0; nt < 8; nt++) {
                uint32_t bb[2];
                int w = (wnP + nt * 8 + gid) * 36 + ks * 8 + tig;
                bb[0] = Vw[w];
                bb[1] = Vw[w + 4];
#pragma unroll
                for (int mt = 0; mt < 2; mt++)
                    mma_f16(accO[mt][nt], a[mt], bb);
            }
        }
        __syncthreads();               // PV done: V (and P) free
        if (c + 1 < NCHUNK) issueV(c + 1);
    }

    // ---- finalize ----
#pragma unroll
    for (int mt = 0; mt < 2; mt++) {
        float il = 1.f / lL[mt][0], ih = 1.f / lL[mt][1];
        int row = q0 + wm + mt * 16 + gid;
#pragma unroll
        for (int nt = 0; nt < 8; nt++) {
            int col = wnP + nt * 8 + 2 * tig;
            *reinterpret_cast<uint32_t*>(&Ob[(long long)row * C2 + col]) =
                pack2(accO[mt][nt][0] * il, accO[mt][nt][1] * il);
            *reinterpret_cast<uint32_t*>(&Ob[(long long)(row + 8) * C2 + col]) =
                pack2(accO[mt][nt][2] * ih, accO[mt][nt][3] * ih);
        }
    }
}

// ---------------------------------------------------------------------------
// x -> fp16
// ---------------------------------------------------------------------------
__global__ void convert_x_kernel(const float* __restrict__ x)
{
    int idx = blockIdx.x * blockDim.x + threadIdx.x;
    const float4 v = reinterpret_cast<const float4*>(x)[idx];
    uint2 u;
    u.x = pack2(v.x, v.y);
    u.y = pack2(v.z, v.w);
    reinterpret_cast<uint2*>(d_Xh)[idx] = u;
}

// ---------------------------------------------------------------------------
// Weights: WcatT [384][512] fp16, WoT [512][256] fp16
// ---------------------------------------------------------------------------
__global__ void concat_w_kernel(const float* __restrict__ wf,
                                const float* __restrict__ wg,
                                const float* __restrict__ wh,
                                const float* __restrict__ wo)
{
    int idx = blockIdx.x * blockDim.x + threadIdx.x;
    const int n1 = NCAT * CC;
    if (idx < n1) {
        int j = idx / CC, k = idx % CC;
        float v;
        if (j < 64)       v = wf[k * C8 + j];
        else if (j < 128) v = wg[k * C8 + (j - 64)];
        else              v = wh[k * C2 + (j - 128)];
        d_WcatT[idx] = __float2half_rn(v);
    } else if (idx < n1 + CC * C2) {
        int i2 = idx - n1;
        int c = i2 / C2, d = i2 % C2;
        d_WoT[i2] = __float2half_rn(wo[d * CC + c]);
    }
}

// ---------------------------------------------------------------------------
// 2x2 max pool from d_Ph: f -> d_Fh [b][p][c], h -> d_Vth [b][d][p]
// ---------------------------------------------------------------------------
__global__ void pool_kernel()
{
    int idx = blockIdx.x * blockDim.x + threadIdx.x;
    const int total = BATCH * NPOOL * (C8 + C2);
    if (idx >= total) return;
    int c = idx % (C8 + C2);
    int p = (idx / (C8 + C2)) % NPOOL;
    int b = idx / ((C8 + C2) * NPOOL);
    int ph = p >> 5, pw = p & 31;
    int col = (c < C8) ? (OFF_F + c) : (OFF_H + (c - C8));
    const __half* base = d_Ph + (long long)b * NPIX * NCAT;
    int r0 = (2 * ph) * WDIM + 2 * pw;
    float v0 = __half2float(base[(long long)r0 * NCAT + col]);
    float v1 = __half2float(base[(long long)(r0 + 1) * NCAT + col]);
    float v2 = __half2float(base[(long long)(r0 + WDIM) * NCAT + col]);
    float v3 = __half2float(base[(long long)(r0 + WDIM + 1) * NCAT + col]);
    __half v = __float2half_rn(fmaxf(fmaxf(v0, v1), fmaxf(v2, v3)));
    if (c < C8) d_Fh[(b * NPOOL + p) * C8 + c] = v;
    else        d_Vth[((long long)b * C2 + (c - C8)) * NPOOL + p] = v;
}

// ---------------------------------------------------------------------------
// Launch
// ---------------------------------------------------------------------------
extern "C" void kernel_launch(void* const* d_in, const int* in_sizes, int n_in,
                              void* d_out, int out_size)
{
    const float* x     = (const float*)d_in[0];
    const float* wf    = (const float*)d_in[1];
    const float* wg    = (const float*)d_in[2];
    const float* wh    = (const float*)d_in[3];
    const float* wo    = (const float*)d_in[4];
    const float* gamma = (const float*)d_in[5];
    float* out = (float*)d_out;

    __half *pXh, *pWcatT, *pWoT, *pPh, *pOh;
    cudaGetSymbolAddress((void**)&pXh, d_Xh);
    cudaGetSymbolAddress((void**)&pWcatT, d_WcatT);
    cudaGetSymbolAddress((void**)&pWoT, d_WoT);
    cudaGetSymbolAddress((void**)&pPh, d_Ph);
    cudaGetSymbolAddress((void**)&pOh, d_Oh);

    cudaFuncSetAttribute(mma_gemm_h<false>,
                         cudaFuncAttributeMaxDynamicSharedMemorySize, SMEM_TOTAL_G);
    cudaFuncSetAttribute(mma_gemm_h<true>,
                         cudaFuncAttributeMaxDynamicSharedMemorySize, SMEM_TOTAL_G);
    cudaFuncSetAttribute(flash_h,
                         cudaFuncAttributeMaxDynamicSharedMemorySize, FLASH_SMEM);

    // 0) x -> fp16
    convert_x_kernel<<<(BATCH * NPIX * CC / 4 + 255) / 256, 256>>>(x);

    // 1) weights -> fp16 transposed
    concat_w_kernel<<<(NCAT * CC + CC * C2 + 255) / 256, 256>>>(wf, wg, wh, wo);

    // 2) P = x @ Wcat  (M=32768, N=384, K=512) -> fp16
    mma_gemm_h<false><<<dim3(NCAT / 64, (BATCH * NPIX) / 256), 256, SMEM_TOTAL_G>>>(
        pXh, CC, pWcatT, CC, pPh, NCAT, CC, nullptr, nullptr);

    // 3) pool -> Fh [b][p][64], Vth [b][256][p]
    pool_kernel<<<(BATCH * NPOOL * (C8 + C2) + 255) / 256, 256>>>();

    // 4-6) fused attention -> Oh fp16
    flash_h<<<dim3(NPIX / FQ, BATCH), 512, FLASH_SMEM>>>();

    // 7) out = gamma * (O @ wo) + x  (M=32768, N=512, K=256)
    mma_gemm_h<true><<<dim3(CC / 64, (BATCH * NPIX) / 256), 256, SMEM_TOTAL_G>>>(
        pOh, C2, pWoT, C2, out, CC, C2, x, gamma);
}

// round 7
// speedup vs baseline: 5.0460x; 1.0905x over previous
#include <cuda_runtime.h>
#include <cuda_fp16.h>
#include <cstdint>
#include <math.h>

// ---------------------------------------------------------------------------
// Problem constants
// ---------------------------------------------------------------------------
#define BATCH 8
#define WDIM 64
#define CC 512
#define C8 64
#define C2 256
#define NPIX 4096
#define NPOOL 1024
#define NCAT 384

// ---------------------------------------------------------------------------
// Scratch (device globals; allocation-free)
// ---------------------------------------------------------------------------
__device__ __half d_Xh[(long long)BATCH * NPIX * CC];     // 32 MB  x fp16
__device__ __half d_WcatT[NCAT * CC];                     // [384][512]
__device__ __half d_WoT[CC * C2];                         // [512][256]
__device__ __half d_Gh[(long long)BATCH * NPIX * C8];     // 4 MB   g full-res [row][64]
__device__ __half d_Fh[BATCH * NPOOL * C8];               // 1 MB   pooled f [p][c]
__device__ __half d_Vth[BATCH * C2 * NPOOL];              // 4 MB   pooled h transposed [d][p]
__device__ __half d_Oh[(long long)BATCH * NPIX * C2];     // 16 MB  attention out

// ---------------------------------------------------------------------------
// Helpers
// ---------------------------------------------------------------------------
__device__ __forceinline__ uint32_t smem_u32(const void* p) {
    uint32_t a;
    asm("{ .reg .u64 t; cvta.to.shared.u64 t, %1; cvt.u32.u64 %0, t; }" : "=r"(a) : "l"(p));
    return a;
}
__device__ __forceinline__ void cp16(uint32_t dst, const void* src) {
    asm volatile("cp.async.cg.shared.global [%0], [%1], 16;" ::"r"(dst), "l"(src));
}
#define CP_COMMIT() asm volatile("cp.async.commit_group;" ::: "memory")
#define CP_WAIT0()  asm volatile("cp.async.wait_group 0;" ::: "memory")
#define CP_WAIT1()  asm volatile("cp.async.wait_group 1;" ::: "memory")

__device__ __forceinline__ void mma_f16(float* d, const uint32_t* a, const uint32_t* b) {
    asm volatile(
        "mma.sync.aligned.m16n8k16.row.col.f32.f16.f16.f32 "
        "{%0,%1,%2,%3}, {%4,%5,%6,%7}, {%8,%9}, {%0,%1,%2,%3};"
        : "+f"(d[0]), "+f"(d[1]), "+f"(d[2]), "+f"(d[3])
        : "r"(a[0]), "r"(a[1]), "r"(a[2]), "r"(a[3]), "r"(b[0]), "r"(b[1]));
}
__device__ __forceinline__ uint32_t pack2(float x, float y) {
    __half2 h = __floats2half2_rn(x, y);
    return *reinterpret_cast<uint32_t*>(&h);
}

// ---------------------------------------------------------------------------
// Shared GEMM config: CTA 256x64, BK=32 halfs, 8 warps (4m x 2n), 3 stages.
// ---------------------------------------------------------------------------
#define HSTR 40
#define HASTG (256 * HSTR * 2)
#define HBSTG (64 * HSTR * 2)
#define HGSTG (HASTG + HBSTG)
#define SMEM_TOTAL_G (3 * HGSTG)

// Mainloop macro-free core used by both GEMMs (hand-inlined in each kernel).

// ---------------------------------------------------------------------------
// Projection GEMM + fused 2x2 max-pool epilogue.
//   P[m, n] = Xh[m, :512] @ WcatT[n, :512]^T   (m over B*4096 pixels, n over 384)
//   n-tile 1 (cols 64..127 = g)  -> d_Gh full-res
//   n-tile 0 (cols 0..63  = f)   -> d_Fh pooled
//   n-tiles 2..5 (cols 128..383 = h) -> d_Vth pooled + transposed
// CTA tile = 256 pixels = 4 image rows -> pooling closes within the CTA.
// ---------------------------------------------------------------------------
#define CSTR 72  // halfs per row of staged C tile (36 words, mod32=4)

__global__ void __launch_bounds__(256, 2) gemm_proj()
{
    extern __shared__ __align__(16) char smem[];
    const int m0 = blockIdx.y * 256;
    const int n0 = blockIdx.x * 64;
    const int tid = threadIdx.x;
    const int wid = tid >> 5, lane = tid & 31;
    const int gid = lane >> 2, tig = lane & 3;
    const int wm = (wid & 3) * 64;
    const int wn = (wid >> 2) * 32;

    const __half* A = d_Xh;
    const __half* Bt = d_WcatT;
    const uint32_t sb = smem_u32(smem);
    const int KT = CC / 32;  // 16

    auto issue = [&](int kt, int s) {
        const uint32_t aB = sb + (uint32_t)(s * HGSTG);
        const uint32_t bB = aB + HASTG;
#pragma unroll
        for (int it = 0; it < 4; it++) {
            int idx = tid + it * 256;
            int r = idx >> 2, q = idx & 3;
            cp16(aB + (uint32_t)(r * 80 + q * 16),
                 A + (long long)(m0 + r) * CC + kt * 32 + q * 8);
        }
        {
            int r = tid >> 2, q = tid & 3;
            cp16(bB + (uint32_t)(r * 80 + q * 16),
                 Bt + (long long)(n0 + r) * CC + kt * 32 + q * 8);
        }
        CP_COMMIT();
    };

    float acc[4][4][4];
#pragma unroll
    for (int i = 0; i < 4; i++)
#pragma unroll
        for (int j = 0; j < 4; j++)
#pragma unroll
            for (int k = 0; k < 4; k++) acc[i][j][k] = 0.f;

    issue(0, 0);
    issue(1, 1);

    for (int kt = 0; kt < KT; kt++) {
        const int s = kt % 3;
        if (kt < KT - 1) CP_WAIT1(); else CP_WAIT0();
        __syncthreads();
        if (kt + 2 < KT) issue(kt + 2, (kt + 2) % 3);

        const uint32_t* AsU = (const uint32_t*)(smem + s * HGSTG);
        const uint32_t* BsU = (const uint32_t*)(smem + s * HGSTG + HASTG);

#pragma unroll
        for (int ks = 0; ks < 2; ks++) {
            uint32_t a[4][4], b[4][2];
#pragma unroll
            for (int mt = 0; mt < 4; mt++) {
                int w = (wm + mt * 16 + gid) * 20 + ks * 8 + tig;
                a[mt][0] = AsU[w];
                a[mt][1] = AsU[w + 8 * 20];
                a[mt][2] = AsU[w + 4];
                a[mt][3] = AsU[w + 8 * 20 + 4];
            }
#pragma unroll
            for (int nt = 0; nt < 4; nt++) {
                int w = (wn + nt * 8 + gid) * 20 + ks * 8 + tig;
                b[nt][0] = BsU[w];
                b[nt][1] = BsU[w + 4];
            }
#pragma unroll
            for (int mt = 0; mt < 4; mt++)
#pragma unroll
                for (int nt = 0; nt < 4; nt++)
                    mma_f16(acc[mt][nt], a[mt], b[nt]);
        }
    }

    // ---- stage C tile (256x64 fp16) in smem (reuse pipeline buffers) ----
    __syncthreads();
    uint32_t* Cw = (uint32_t*)smem;
#pragma unroll
    for (int mt = 0; mt < 4; mt++)
#pragma unroll
        for (int h = 0; h < 2; h++) {
            int row = wm + mt * 16 + gid + h * 8;
#pragma unroll
            for (int nt = 0; nt < 4; nt++)
                Cw[row * (CSTR / 2) + wn / 2 + nt * 4 + tig] =
                    pack2(acc[mt][nt][h * 2], acc[mt][nt][h * 2 + 1]);
        }
    __syncthreads();

    const __half* Cs = (const __half*)smem;
    const int b = m0 >> 12;          // batch
    const int pix0 = m0 & 4095;
    const int pr0 = pix0 >> 7;       // pooled row base (pix0/64/2); CTA covers 2 pooled rows

    if (n0 == 64) {
        // ---- g: full-res to d_Gh ----
        __half* G = d_Gh + (long long)m0 * C8;
#pragma unroll
        for (int it = 0; it < 8; it++) {
            int idx = tid + it * 256;
            int row = idx >> 3, q = idx & 7;
            uint4 v = *reinterpret_cast<const uint4*>(&Cw[row * (CSTR / 2) + q * 4]);
            *reinterpret_cast<uint4*>(&G[row * C8 + q * 8]) = v;
        }
    } else if (n0 == 0) {
        // ---- f: 2x2 pool -> d_Fh [b][p][c] (half2 along c) ----
        __half* F = d_Fh + (b * NPOOL + pr0 * 32) * C8;
        const __half2* C2s = (const __half2*)Cs;
#pragma unroll
        for (int it = 0; it < 8; it++) {
            int idx = tid + it * 256;
            int p = idx >> 5, c2 = idx & 31;        // p 0..63, c2 0..31
            int base = ((p >> 5) * 2) * 64 + (p & 31) * 2;  // local pixel row
            __half2 v0 = C2s[(base)*(CSTR / 2) + c2];
            __half2 v1 = C2s[(base + 1) * (CSTR / 2) + c2];
            __half2 v2 = C2s[(base + 64) * (CSTR / 2) + c2];
            __half2 v3 = C2s[(base + 65) * (CSTR / 2) + c2];
            __half2 v = __hmax2(__hmax2(v0, v1), __hmax2(v2, v3));
            *reinterpret_cast<__half2*>(&F[p * C8 + 2 * c2]) = v;
        }
    } else {
        // ---- h: 2x2 pool + transpose -> d_Vth [b][d][p] ----
        int c = tid & 63;            // channel within tile
        int pgrp = tid >> 6;         // 4 groups x 16 pooled pixels
        int d = n0 - 128 + c;
        __half buf[16];
#pragma unroll
        for (int j = 0; j < 16; j++) {
            int p = pgrp * 16 + j;
            int base = ((p >> 5) * 2) * 64 + (p & 31) * 2;
            __half v0 = Cs[(base)*CSTR + c];
            __half v1 = Cs[(base + 1) * CSTR + c];
            __half v2 = Cs[(base + 64) * CSTR + c];
            __half v3 = Cs[(base + 65) * CSTR + c];
            buf[j] = __hmax(__hmax(v0, v1), __hmax(v2, v3));
        }
        __half* dst = d_Vth + ((long long)b * C2 + d) * NPOOL + pr0 * 32 + pgrp * 16;
        *reinterpret_cast<uint4*>(dst) = *reinterpret_cast<uint4*>(buf);
        *reinterpret_cast<uint4*>(dst + 8) = *reinterpret_cast<uint4*>(buf + 8);
    }
}

// ---------------------------------------------------------------------------
// Output GEMM: out = gamma * (Oh @ WoT^T) + x   (M=32768, N=512, K=256)
// ---------------------------------------------------------------------------
__global__ void __launch_bounds__(256, 2) gemm_out(
    const float* __restrict__ resid, const float* __restrict__ gamma,
    float* __restrict__ C)
{
    extern __shared__ __align__(16) char smem[];
    const int m0 = blockIdx.y * 256;
    const int n0 = blockIdx.x * 64;
    const int tid = threadIdx.x;
    const int wid = tid >> 5, lane = tid & 31;
    const int gid = lane >> 2, tig = lane & 3;
    const int wm = (wid & 3) * 64;
    const int wn = (wid >> 2) * 32;

    const __half* A = d_Oh;
    const __half* Bt = d_WoT;
    const uint32_t sb = smem_u32(smem);
    const int KT = C2 / 32;  // 8

    auto issue = [&](int kt, int s) {
        const uint32_t aB = sb + (uint32_t)(s * HGSTG);
        const uint32_t bB = aB + HASTG;
#pragma unroll
        for (int it = 0; it < 4; it++) {
            int idx = tid + it * 256;
            int r = idx >> 2, q = idx & 3;
            cp16(aB + (uint32_t)(r * 80 + q * 16),
                 A + (long long)(m0 + r) * C2 + kt * 32 + q * 8);
        }
        {
            int r = tid >> 2, q = tid & 3;
            cp16(bB + (uint32_t)(r * 80 + q * 16),
                 Bt + (long long)(n0 + r) * C2 + kt * 32 + q * 8);
        }
        CP_COMMIT();
    };

    float acc[4][4][4];
#pragma unroll
    for (int i = 0; i < 4; i++)
#pragma unroll
        for (int j = 0; j < 4; j++)
#pragma unroll
            for (int k = 0; k < 4; k++) acc[i][j][k] = 0.f;

    issue(0, 0);
    issue(1, 1);

    for (int kt = 0; kt < KT; kt++) {
        const int s = kt % 3;
        if (kt < KT - 1) CP_WAIT1(); else CP_WAIT0();
        __syncthreads();
        if (kt + 2 < KT) issue(kt + 2, (kt + 2) % 3);

        const uint32_t* AsU = (const uint32_t*)(smem + s * HGSTG);
        const uint32_t* BsU = (const uint32_t*)(smem + s * HGSTG + HASTG);

#pragma unroll
        for (int ks = 0; ks < 2; ks++) {
            uint32_t a[4][4], b[4][2];
#pragma unroll
            for (int mt = 0; mt < 4; mt++) {
                int w = (wm + mt * 16 + gid) * 20 + ks * 8 + tig;
                a[mt][0] = AsU[w];
                a[mt][1] = AsU[w + 8 * 20];
                a[mt][2] = AsU[w + 4];
                a[mt][3] = AsU[w + 8 * 20 + 4];
            }
#pragma unroll
            for (int nt = 0; nt < 4; nt++) {
                int w = (wn + nt * 8 + gid) * 20 + ks * 8 + tig;
                b[nt][0] = BsU[w];
                b[nt][1] = BsU[w + 4];
            }
#pragma unroll
            for (int mt = 0; mt < 4; mt++)
#pragma unroll
                for (int nt = 0; nt < 4; nt++)
                    mma_f16(acc[mt][nt], a[mt], b[nt]);
        }
    }

    const float gm = gamma[0];
#pragma unroll
    for (int mt = 0; mt < 4; mt++)
#pragma unroll
        for (int h = 0; h < 2; h++) {
            long long row = m0 + wm + mt * 16 + gid + h * 8;
#pragma unroll
            for (int nt = 0; nt < 4; nt++) {
                long long off = row * CC + n0 + wn + nt * 8 + 2 * tig;
                float2 rv = *reinterpret_cast<const float2*>(&resid[off]);
                float2 v;
                v.x = fmaf(gm, acc[mt][nt][h * 2], rv.x);
                v.y = fmaf(gm, acc[mt][nt][h * 2 + 1], rv.y);
                *reinterpret_cast<float2*>(&C[off]) = v;
            }
        }
}

// ---------------------------------------------------------------------------
// Flash attention (fp16, fp32 acc): 512 thr, 128 q/CTA, 16 chunks of 64.
// ---------------------------------------------------------------------------
#define FQ 128
#define NCHUNK 16
#define SM_Q 0
#define SM_P 18432
#define SM_K 36864
#define SM_V 46080
#define SM_RM 82944
#define SM_RS 84992
#define FLASH_SMEM 87040

__global__ void __launch_bounds__(512, 1) flash_h()
{
    extern __shared__ __align__(16) char fsm[];
    const uint32_t sb = smem_u32(fsm);

    const int b = blockIdx.y;
    const int q0 = blockIdx.x * FQ;
    const __half* Qg = d_Gh + ((long long)b * NPIX + q0) * C8;
    const __half* Fb = d_Fh + b * NPOOL * C8;
    const __half* Vtb = d_Vth + (long long)b * C2 * NPOOL;
    __half* Ob = d_Oh + (long long)b * NPIX * C2;

    const int tid = threadIdx.x;
    const int wid = tid >> 5, lane = tid & 31;
    const int gid = lane >> 2, tig = lane & 3;
    const int wm = (wid & 3) * 32;
    const int wgrp = wid >> 2;
    const int wnS = wgrp * 16;
    const int wnP = wgrp * 64;

    auto issueK = [&](int c) {
        int r = tid >> 3, q = tid & 7;
        cp16(sb + SM_K + (uint32_t)(r * 144 + q * 16),
             Fb + (c * 64 + r) * C8 + q * 8);
        CP_COMMIT();
    };
    auto issueV = [&](int c) {
#pragma unroll
        for (int it = 0; it < 4; it++) {
            int idx = tid + it * 512;
            int r = idx >> 3, q = idx & 7;
            cp16(sb + SM_V + (uint32_t)(r * 144 + q * 16),
                 Vtb + (long long)r * NPOOL + c * 64 + q * 8);
        }
        CP_COMMIT();
    };

    {
#pragma unroll
        for (int it = 0; it < 2; it++) {
            int idx = tid + it * 512;
            int r = idx >> 3, q = idx & 7;
            cp16(sb + SM_Q + (uint32_t)(r * 144 + q * 16),
                 Qg + (long long)r * C8 + q * 8);
        }
        issueK(0);
        issueV(0);
    }

    float accO[2][8][4];
#pragma unroll
    for (int m = 0; m < 2; m++)
#pragma unroll
        for (int n = 0; n < 8; n++)
#pragma unroll
            for (int k = 0; k < 4; k++) accO[m][n][k] = 0.f;
    float mM[2][2] = {{-1e30f, -1e30f}, {-1e30f, -1e30f}};
    float lL[2][2] = {{0.f, 0.f}, {0.f, 0.f}};

    const uint32_t* Qw = (const uint32_t*)(fsm + SM_Q);
    const uint32_t* Kw = (const uint32_t*)(fsm + SM_K);
    const uint32_t* Vw = (const uint32_t*)(fsm + SM_V);
    uint32_t* Pw = (uint32_t*)(fsm + SM_P);
    float* redm = (float*)(fsm + SM_RM);
    float* reds = (float*)(fsm + SM_RS);

    for (int c = 0; c < NCHUNK; c++) {
        CP_WAIT1();
        __syncthreads();

        float accS[2][2][4];
#pragma unroll
        for (int m = 0; m < 2; m++)
#pragma unroll
            for (int n = 0; n < 2; n++)
#pragma unroll
                for (int k = 0; k < 4; k++) accS[m][n][k] = 0.f;
#pragma unroll
        for (int ks = 0; ks < 4; ks++) {
            uint32_t a[2][4], bb[2][2];
#pragma unroll
            for (int mt = 0; mt < 2; mt++) {
                int w = (wm + mt * 16 + gid) * 36 + ks * 8 + tig;
                a[mt][0] = Qw[w];
                a[mt][1] = Qw[w + 8 * 36];
                a[mt][2] = Qw[w + 4];
                a[mt][3] = Qw[w + 8 * 36 + 4];
            }
#pragma unroll
            for (int nt = 0; nt < 2; nt++) {
                int w = (wnS + nt * 8 + gid) * 36 + ks * 8 + tig;
                bb[nt][0] = Kw[w];
                bb[nt][1] = Kw[w + 4];
            }
#pragma unroll
            for (int mt = 0; mt < 2; mt++)
#pragma unroll
                for (int nt = 0; nt < 2; nt++)
                    mma_f16(accS[mt][nt], a[mt], bb[nt]);
        }

#pragma unroll
        for (int mt = 0; mt < 2; mt++) {
            float cl = fmaxf(fmaxf(accS[mt][0][0], accS[mt][0][1]),
                             fmaxf(accS[mt][1][0], accS[mt][1][1]));
            float ch = fmaxf(fmaxf(accS[mt][0][2], accS[mt][0][3]),
                             fmaxf(accS[mt][1][2], accS[mt][1][3]));
#pragma unroll
            for (int o = 1; o <= 2; o <<= 1) {
                cl = fmaxf(cl, __shfl_xor_sync(0xffffffffu, cl, o));
                ch = fmaxf(ch, __shfl_xor_sync(0xffffffffu, ch, o));
            }
            if (tig == 0) {
                redm[wgrp * FQ + wm + mt * 16 + gid] = cl;
                redm[wgrp * FQ + wm + mt * 16 + gid + 8] = ch;
            }
        }
        __syncthreads();
        if (c + 1 < NCHUNK) issueK(c + 1);

        float sc[2][2];
#pragma unroll
        for (int mt = 0; mt < 2; mt++)
#pragma unroll
            for (int h = 0; h < 2; h++) {
                int row = wm + mt * 16 + gid + h * 8;
                float mc = fmaxf(fmaxf(redm[row], redm[FQ + row]),
                                 fmaxf(redm[2 * FQ + row], redm[3 * FQ + row]));
                float mn = fmaxf(mM[mt][h], mc);
                sc[mt][h] = __expf(mM[mt][h] - mn);
                mM[mt][h] = mn;
            }

        float ps[2][2] = {{0.f, 0.f}, {0.f, 0.f}};
#pragma unroll
        for (int mt = 0; mt < 2; mt++) {
            int row = wm + mt * 16 + gid;
#pragma unroll
            for (int nt = 0; nt < 2; nt++) {
                float e0 = __expf(accS[mt][nt][0] - mM[mt][0]);
                float e1 = __expf(accS[mt][nt][1] - mM[mt][0]);
                float e2 = __expf(accS[mt][nt][2] - mM[mt][1]);
                float e3 = __expf(accS[mt][nt][3] - mM[mt][1]);
                ps[mt][0] += e0 + e1;
                ps[mt][1] += e2 + e3;
                int w = row * 36 + wgrp * 8 + nt * 4 + tig;
                Pw[w] = pack2(e0, e1);
                Pw[w + 8 * 36] = pack2(e2, e3);
            }
        }
#pragma unroll
        for (int mt = 0; mt < 2; mt++) {
#pragma unroll
            for (int o = 1; o <= 2; o <<= 1) {
                ps[mt][0] += __shfl_xor_sync(0xffffffffu, ps[mt][0], o);
                ps[mt][1] += __shfl_xor_sync(0xffffffffu, ps[mt][1], o);
            }
            if (tig == 0) {
                reds[wgrp * FQ + wm + mt * 16 + gid] = ps[mt][0];
                reds[wgrp * FQ + wm + mt * 16 + gid + 8] = ps[mt][1];
            }
        }
        __syncthreads();
#pragma unroll
        for (int mt = 0; mt < 2; mt++)
#pragma unroll
            for (int h = 0; h < 2; h++) {
                int row = wm + mt * 16 + gid + h * 8;
                float su = reds[row] + reds[FQ + row] +
                           reds[2 * FQ + row] + reds[3 * FQ + row];
                lL[mt][h] = lL[mt][h] * sc[mt][h] + su;
            }

#pragma unroll
        for (int mt = 0; mt < 2; mt++)
#pragma unroll
            for (int nt = 0; nt < 8; nt++) {
                accO[mt][nt][0] *= sc[mt][0];
                accO[mt][nt][1] *= sc[mt][0];
                accO[mt][nt][2] *= sc[mt][1];
                accO[mt][nt][3] *= sc[mt][1];
            }

        if (c + 1 < NCHUNK) CP_WAIT1(); else CP_WAIT0();
        __syncthreads();

#pragma unroll
        for (int ks = 0; ks < 4; ks++) {
            uint32_t a[2][4];
#pragma unroll
            for (int mt = 0; mt < 2; mt++) {
                int w = (wm + mt * 16 + gid) * 36 + ks * 8 + tig;
                a[mt][0] = Pw[w];
                a[mt][1] = Pw[w + 8 * 36];
                a[mt][2] = Pw[w + 4];
                a[mt][3] = Pw[w + 8 * 36 + 4];
            }
#pragma unroll
            for (int nt = 0; nt < 8; nt++) {
                uint32_t bb[2];
                int w = (wnP + nt * 8 + gid) * 36 + ks * 8 + tig;
                bb[0] = Vw[w];
                bb[1] = Vw[w + 4];
#pragma unroll
                for (int mt = 0; mt < 2; mt++)
                    mma_f16(accO[mt][nt], a[mt], bb);
            }
        }
        __syncthreads();
        if (c + 1 < NCHUNK) issueV(c + 1);
    }

#pragma unroll
    for (int mt = 0; mt < 2; mt++) {
        float il = 1.f / lL[mt][0], ih = 1.f / lL[mt][1];
        int row = q0 + wm + mt * 16 + gid;
#pragma unroll
        for (int nt = 0; nt < 8; nt++) {
            int col = wnP + nt * 8 + 2 * tig;
            *reinterpret_cast<uint32_t*>(&Ob[(long long)row * C2 + col]) =
                pack2(accO[mt][nt][0] * il, accO[mt][nt][1] * il);
            *reinterpret_cast<uint32_t*>(&Ob[(long long)(row + 8) * C2 + col]) =
                pack2(accO[mt][nt][2] * ih, accO[mt][nt][3] * ih);
        }
    }
}

// ---------------------------------------------------------------------------
// x -> fp16
// ---------------------------------------------------------------------------
__global__ void convert_x_kernel(const float* __restrict__ x)
{
    int idx = blockIdx.x * blockDim.x + threadIdx.x;
    const float4 v = reinterpret_cast<const float4*>(x)[idx];
    uint2 u;
    u.x = pack2(v.x, v.y);
    u.y = pack2(v.z, v.w);
    reinterpret_cast<uint2*>(d_Xh)[idx] = u;
}

// ---------------------------------------------------------------------------
// Weights: WcatT [384][512] fp16, WoT [512][256] fp16
// ---------------------------------------------------------------------------
__global__ void concat_w_kernel(const float* __restrict__ wf,
                                const float* __restrict__ wg,
                                const float* __restrict__ wh,
                                const float* __restrict__ wo)
{
    int idx = blockIdx.x * blockDim.x + threadIdx.x;
    const int n1 = NCAT * CC;
    if (idx < n1) {
        int j = idx / CC, k = idx % CC;
        float v;
        if (j < 64)       v = wf[k * C8 + j];
        else if (j < 128) v = wg[k * C8 + (j - 64)];
        else              v = wh[k * C2 + (j - 128)];
        d_WcatT[idx] = __float2half_rn(v);
    } else if (idx < n1 + CC * C2) {
        int i2 = idx - n1;
        int c = i2 / C2, d = i2 % C2;
        d_WoT[i2] = __float2half_rn(wo[d * CC + c]);
    }
}

// ---------------------------------------------------------------------------
// Launch
// ---------------------------------------------------------------------------
extern "C" void kernel_launch(void* const* d_in, const int* in_sizes, int n_in,
                              void* d_out, int out_size)
{
    const float* x     = (const float*)d_in[0];
    const float* wf    = (const float*)d_in[1];
    const float* wg    = (const float*)d_in[2];
    const float* wh    = (const float*)d_in[3];
    const float* wo    = (const float*)d_in[4];
    const float* gamma = (const float*)d_in[5];
    float* out = (float*)d_out;

    cudaFuncSetAttribute(gemm_proj,
                         cudaFuncAttributeMaxDynamicSharedMemorySize, SMEM_TOTAL_G);
    cudaFuncSetAttribute(gemm_out,
                         cudaFuncAttributeMaxDynamicSharedMemorySize, SMEM_TOTAL_G);
    cudaFuncSetAttribute(flash_h,
                         cudaFuncAttributeMaxDynamicSharedMemorySize, FLASH_SMEM);

    // 0) x -> fp16
    convert_x_kernel<<<(BATCH * NPIX * CC / 4 + 255) / 256, 256>>>(x);

    // 1) weights -> fp16 transposed
    concat_w_kernel<<<(NCAT * CC + CC * C2 + 255) / 256, 256>>>(wf, wg, wh, wo);

    // 2+3) projection GEMM with fused pooling epilogue
    gemm_proj<<<dim3(NCAT / 64, (BATCH * NPIX) / 256), 256, SMEM_TOTAL_G>>>();

    // 4-6) fused attention -> Oh fp16
    flash_h<<<dim3(NPIX / FQ, BATCH), 512, FLASH_SMEM>>>();

    // 7) out = gamma * (Oh @ wo) + x
    gemm_out<<<dim3(CC / 64, (BATCH * NPIX) / 256), 256, SMEM_TOTAL_G>>>(x, gamma, out);
}